// round 1
// baseline (speedup 1.0000x reference)
#include <cuda_runtime.h>
#include <cuda_bf16.h>
#include <math.h>

// Problem constants
#define B_    2
#define S_    2048
#define DIM_  2048
#define NH_   32
#define NKV_  8
#define HD_   64
#define M_    (B_ * S_)        // 4096 rows

// ---------------------------------------------------------------------------
// Scratch (static device globals — no allocation allowed)
// ---------------------------------------------------------------------------
__device__ float g_q[M_ * NH_ * HD_];     // [4096, 2048]
__device__ float g_k[M_ * NKV_ * HD_];    // [4096, 512]
__device__ float g_v[M_ * NKV_ * HD_];    // [4096, 512]
__device__ float g_ctx[M_ * NH_ * HD_];   // [4096, 2048]
__device__ int   g_dstart[B_ * 8];        // first index of each doc per batch

// ---------------------------------------------------------------------------
// SGEMM: C[M,N] = A[M,K] * B[N,K]^T   (all row-major, M,N multiples of 128,
// K multiple of 8). 128x128 tile, 256 threads, 8x8 per thread.
// ---------------------------------------------------------------------------
__global__ __launch_bounds__(256) void sgemm_abt(const float* __restrict__ A,
                                                 const float* __restrict__ Bm,
                                                 float* __restrict__ C,
                                                 int M, int N, int K)
{
    __shared__ float As[8][128];
    __shared__ float Bs[8][128];

    const int tid = threadIdx.x;
    const int tx = tid & 15;
    const int ty = tid >> 4;
    const int bx = blockIdx.x * 128;
    const int by = blockIdx.y * 128;

    const int lr = tid >> 1;          // 0..127
    const int lc = (tid & 1) * 4;     // 0 or 4

    const float* Ag = A  + (size_t)(by + lr) * K + lc;
    const float* Bg = Bm + (size_t)(bx + lr) * K + lc;

    float acc[8][8];
#pragma unroll
    for (int i = 0; i < 8; ++i)
#pragma unroll
        for (int j = 0; j < 8; ++j) acc[i][j] = 0.f;

    for (int k0 = 0; k0 < K; k0 += 8) {
        float4 av = *(const float4*)(Ag + k0);
        float4 bv = *(const float4*)(Bg + k0);
        __syncthreads();
        As[lc + 0][lr] = av.x; As[lc + 1][lr] = av.y;
        As[lc + 2][lr] = av.z; As[lc + 3][lr] = av.w;
        Bs[lc + 0][lr] = bv.x; Bs[lc + 1][lr] = bv.y;
        Bs[lc + 2][lr] = bv.z; Bs[lc + 3][lr] = bv.w;
        __syncthreads();
#pragma unroll
        for (int kk = 0; kk < 8; ++kk) {
            float af[8], bf[8];
#pragma unroll
            for (int i = 0; i < 8; ++i) af[i] = As[kk][ty * 8 + i];
#pragma unroll
            for (int j = 0; j < 8; ++j) bf[j] = Bs[kk][tx * 8 + j];
#pragma unroll
            for (int i = 0; i < 8; ++i)
#pragma unroll
                for (int j = 0; j < 8; ++j)
                    acc[i][j] = fmaf(af[i], bf[j], acc[i][j]);
        }
    }

#pragma unroll
    for (int i = 0; i < 8; ++i) {
        float* Cp = C + (size_t)(by + ty * 8 + i) * N + bx + tx * 8;
        *(float4*)(Cp + 0) = make_float4(acc[i][0], acc[i][1], acc[i][2], acc[i][3]);
        *(float4*)(Cp + 4) = make_float4(acc[i][4], acc[i][5], acc[i][6], acc[i][7]);
    }
}

// ---------------------------------------------------------------------------
// RoPE (in-place). t layout: [B, S, nh, HD]. half = HD/2 = 32.
// ---------------------------------------------------------------------------
__global__ void rope_kernel(float* __restrict__ t,
                            const float* __restrict__ cs,
                            const float* __restrict__ sn,
                            int nh, int total)
{
    int i = blockIdx.x * blockDim.x + threadIdx.x;
    if (i >= total) return;
    int d = i & 31;
    int g = i >> 5;              // b*(S*nh) + s*nh + h
    int h = g % nh;
    int s = (g / nh) % S_;
    int b = g / (nh * S_);
    float c  = cs[s * 32 + d];
    float sv = sn[s * 32 + d];
    float* base = t + (((size_t)(b * S_ + s) * nh + h) * HD_);
    float x1 = base[d];
    float x2 = base[d + 32];
    base[d]      = x1 * c - x2 * sv;
    base[d + 32] = x2 * c + x1 * sv;
}

// ---------------------------------------------------------------------------
// Doc start scan: g_dstart[b*8 + d] = first s with doc_ids[b,s] == d
// ---------------------------------------------------------------------------
__global__ void docstart_kernel(const int* __restrict__ doc)
{
    int i = blockIdx.x * blockDim.x + threadIdx.x;
    if (i >= B_ * S_) return;
    int s = i & (S_ - 1);
    int d = doc[i];
    if (s == 0 || doc[i - 1] != d) g_dstart[(i >> 11) * 8 + d] = s;
}

// ---------------------------------------------------------------------------
// Flash attention (fp32), doc mask + causal, doc-start skipping.
// Tile: 64 queries x 64 keys x HD=64. 256 threads, 16x16 grid, 4x4 per thread.
// ---------------------------------------------------------------------------
__global__ __launch_bounds__(256) void flash_kernel(const int* __restrict__ doc,
                                                    float* __restrict__ ctx)
{
    extern __shared__ float sm[];
    float* Qs = sm;                  // 64*65
    float* Ks = Qs + 64 * 65;        // 64*65
    float* Vs = Ks + 64 * 65;        // 64*65
    float* Ps = Vs + 64 * 65;        // 64*65
    __shared__ int qdoc[64];
    __shared__ int kdoc[64];

    const int qb  = blockIdx.x;
    const int h   = blockIdx.y;
    const int b   = blockIdx.z;
    const int kvh = h >> 2;          // N_REP = 4
    const int tid = threadIdx.x;
    const int tx  = tid & 15;
    const int ty  = tid >> 4;
    const int q0  = qb * 64;
    const int r0  = ty * 4;
    const int c0  = tx * 4;

    // Load Q tile (pre-scaled by 1/sqrt(HD) = 0.125) and query doc ids.
    for (int idx = tid; idx < 64 * 64; idx += 256) {
        int r = idx >> 6, d = idx & 63;
        Qs[r * 65 + d] =
            g_q[(((size_t)(b * S_ + q0 + r)) * NH_ + h) * HD_ + d] * 0.125f;
    }
    if (tid < 64) qdoc[tid] = doc[b * S_ + q0 + tid];
    __syncthreads();

    const int kb0 = g_dstart[b * 8 + qdoc[0]] >> 6;

    float m[4], l[4], acc[4][4];
#pragma unroll
    for (int i = 0; i < 4; ++i) {
        m[i] = -1e30f;
        l[i] = 0.f;
#pragma unroll
        for (int j = 0; j < 4; ++j) acc[i][j] = 0.f;
    }

    for (int kb = kb0; kb <= qb; ++kb) {
        // Load K, V tiles + key doc ids
        for (int idx = tid; idx < 64 * 64; idx += 256) {
            int r = idx >> 6, d = idx & 63;
            size_t g = (((size_t)(b * S_ + kb * 64 + r)) * NKV_ + kvh) * HD_ + d;
            Ks[r * 65 + d] = g_k[g];
            Vs[r * 65 + d] = g_v[g];
        }
        if (tid < 64) kdoc[tid] = doc[b * S_ + kb * 64 + tid];
        __syncthreads();

        // S = Q * K^T  (4x4 per thread)
        float sc[4][4];
#pragma unroll
        for (int i = 0; i < 4; ++i)
#pragma unroll
            for (int j = 0; j < 4; ++j) sc[i][j] = 0.f;

#pragma unroll 8
        for (int d = 0; d < 64; ++d) {
            float qf[4], kf[4];
#pragma unroll
            for (int i = 0; i < 4; ++i) qf[i] = Qs[(r0 + i) * 65 + d];
#pragma unroll
            for (int j = 0; j < 4; ++j) kf[j] = Ks[(c0 + j) * 65 + d];
#pragma unroll
            for (int i = 0; i < 4; ++i)
#pragma unroll
                for (int j = 0; j < 4; ++j)
                    sc[i][j] = fmaf(qf[i], kf[j], sc[i][j]);
        }

        // mask: causal + same-doc
#pragma unroll
        for (int i = 0; i < 4; ++i) {
            int qi = q0 + r0 + i;
            int qd = qdoc[r0 + i];
#pragma unroll
            for (int j = 0; j < 4; ++j) {
                int kj = kb * 64 + c0 + j;
                if (kj > qi || kdoc[c0 + j] != qd) sc[i][j] = -1e30f;
            }
        }

        // online softmax update (per row, replicated over the 16 tx lanes)
#pragma unroll
        for (int i = 0; i < 4; ++i) {
            float rm = sc[i][0];
            rm = fmaxf(rm, sc[i][1]);
            rm = fmaxf(rm, sc[i][2]);
            rm = fmaxf(rm, sc[i][3]);
#pragma unroll
            for (int off = 8; off; off >>= 1)
                rm = fmaxf(rm, __shfl_xor_sync(0xffffffffu, rm, off));
            float mn = fmaxf(m[i], rm);
            float corr = __expf(m[i] - mn);
            float rs = 0.f;
#pragma unroll
            for (int j = 0; j < 4; ++j) {
                sc[i][j] = __expf(sc[i][j] - mn);
                rs += sc[i][j];
            }
#pragma unroll
            for (int off = 8; off; off >>= 1)
                rs += __shfl_xor_sync(0xffffffffu, rs, off);
            l[i] = l[i] * corr + rs;
            m[i] = mn;
#pragma unroll
            for (int j = 0; j < 4; ++j) acc[i][j] *= corr;
        }

        // stage P tile
#pragma unroll
        for (int i = 0; i < 4; ++i)
#pragma unroll
            for (int j = 0; j < 4; ++j)
                Ps[(r0 + i) * 65 + c0 + j] = sc[i][j];
        __syncthreads();

        // acc += P * V
#pragma unroll 8
        for (int c = 0; c < 64; ++c) {
            float pf[4], vf[4];
#pragma unroll
            for (int i = 0; i < 4; ++i) pf[i] = Ps[(r0 + i) * 65 + c];
#pragma unroll
            for (int j = 0; j < 4; ++j) vf[j] = Vs[c * 65 + c0 + j];
#pragma unroll
            for (int i = 0; i < 4; ++i)
#pragma unroll
                for (int j = 0; j < 4; ++j)
                    acc[i][j] = fmaf(pf[i], vf[j], acc[i][j]);
        }
        __syncthreads();   // before K/V/P overwrite next iteration
    }

    // epilogue: ctx[b, q, h, :] = acc / l
#pragma unroll
    for (int i = 0; i < 4; ++i) {
        float inv = 1.0f / l[i];
        size_t base = (((size_t)(b * S_ + q0 + r0 + i)) * NH_ + h) * HD_ + c0;
#pragma unroll
        for (int j = 0; j < 4; ++j)
            ctx[base + j] = acc[i][j] * inv;
    }
}

// ---------------------------------------------------------------------------
// Host launcher
// ---------------------------------------------------------------------------
extern "C" void kernel_launch(void* const* d_in, const int* in_sizes, int n_in,
                              void* d_out, int out_size)
{
    const float* x   = (const float*)d_in[0];
    const float* rc  = (const float*)d_in[1];
    const float* rs  = (const float*)d_in[2];
    const int*   doc = (const int*)d_in[3];
    const float* Wq  = (const float*)d_in[4];
    const float* Wk  = (const float*)d_in[5];
    const float* Wv  = (const float*)d_in[6];
    const float* Wo  = (const float*)d_in[7];
    float* out = (float*)d_out;

    float *q_p, *k_p, *v_p, *ctx_p;
    cudaGetSymbolAddress((void**)&q_p,   g_q);
    cudaGetSymbolAddress((void**)&k_p,   g_k);
    cudaGetSymbolAddress((void**)&v_p,   g_v);
    cudaGetSymbolAddress((void**)&ctx_p, g_ctx);

    const int flash_smem = 4 * 64 * 65 * (int)sizeof(float);   // 66560 B
    cudaFuncSetAttribute(flash_kernel,
                         cudaFuncAttributeMaxDynamicSharedMemorySize,
                         flash_smem);

    // QKV projections
    {
        dim3 gq(NH_ * HD_ / 128, M_ / 128);   // (16, 32)
        sgemm_abt<<<gq, 256>>>(x, Wq, q_p, M_, NH_ * HD_, DIM_);
        dim3 gk(NKV_ * HD_ / 128, M_ / 128);  // (4, 32)
        sgemm_abt<<<gk, 256>>>(x, Wk, k_p, M_, NKV_ * HD_, DIM_);
        sgemm_abt<<<gk, 256>>>(x, Wv, v_p, M_, NKV_ * HD_, DIM_);
    }

    // RoPE on Q and K
    {
        int tq = B_ * S_ * NH_ * 32;
        rope_kernel<<<(tq + 255) / 256, 256>>>(q_p, rc, rs, NH_, tq);
        int tk = B_ * S_ * NKV_ * 32;
        rope_kernel<<<(tk + 255) / 256, 256>>>(k_p, rc, rs, NKV_, tk);
    }

    // doc start offsets
    docstart_kernel<<<(B_ * S_ + 255) / 256, 256>>>(doc);

    // flash attention
    {
        dim3 g(S_ / 64, NH_, B_);             // (32, 32, 2)
        flash_kernel<<<g, 256, flash_smem>>>(doc, ctx_p);
    }

    // output projection
    {
        dim3 go(DIM_ / 128, M_ / 128);        // (16, 32)
        sgemm_abt<<<go, 256>>>(ctx_p, Wo, out, M_, DIM_, DIM_);
    }
}

// round 2
// speedup vs baseline: 1.7092x; 1.7092x over previous
#include <cuda_runtime.h>
#include <cuda_bf16.h>
#include <mma.h>
#include <math.h>

using namespace nvcuda;

// Problem constants
#define B_    2
#define S_    2048
#define DIM_  2048
#define NH_   32
#define NKV_  8
#define HD_   64
#define M_    (B_ * S_)        // 4096 rows

// ---------------------------------------------------------------------------
// Scratch (static device globals — no allocation allowed)
// ---------------------------------------------------------------------------
__device__ float g_q[M_ * NH_ * HD_];     // [4096, 2048]
__device__ float g_k[M_ * NKV_ * HD_];    // [4096, 512]
__device__ float g_v[M_ * NKV_ * HD_];    // [4096, 512]
__device__ float g_ctx[M_ * NH_ * HD_];   // [4096, 2048]
__device__ int   g_dstart[B_ * 8];

// bf16 hi/lo split copies
__device__ __nv_bfloat16 g_xhi[M_ * DIM_],  g_xlo[M_ * DIM_];
__device__ __nv_bfloat16 g_wqhi[DIM_ * DIM_], g_wqlo[DIM_ * DIM_];
__device__ __nv_bfloat16 g_wkhi[512 * DIM_],  g_wklo[512 * DIM_];
__device__ __nv_bfloat16 g_wvhi[512 * DIM_],  g_wvlo[512 * DIM_];
__device__ __nv_bfloat16 g_wohi[DIM_ * DIM_], g_wolo[DIM_ * DIM_];
__device__ __nv_bfloat16 g_chi[M_ * DIM_],  g_clo[M_ * DIM_];

// ---------------------------------------------------------------------------
// fp32 -> bf16 (hi) + bf16 (residual lo)
// ---------------------------------------------------------------------------
__global__ void split_kernel(const float* __restrict__ src,
                             __nv_bfloat16* __restrict__ hi,
                             __nv_bfloat16* __restrict__ lo, int n)
{
    int i = blockIdx.x * blockDim.x + threadIdx.x;
    if (i >= n) return;
    float v = src[i];
    __nv_bfloat16 h = __float2bfloat16(v);
    hi[i] = h;
    lo[i] = __float2bfloat16(v - __bfloat162float(h));
}

// ---------------------------------------------------------------------------
// bf16-split GEMM: C[M,N] = A[M,K] * B[N,K]^T  (fp32 accumulate)
// 128x128 block tile, KC=32 chunks, 8 warps; warp tile 64x32.
// C = Ahi*Bhi + Ahi*Blo + Alo*Bhi   (error ~2^-16)
// ---------------------------------------------------------------------------
#define KC  32
#define LDA 48   // padded leading dim in smem (bf16 elems)

__global__ __launch_bounds__(256) void gemm_bf16split(
    const __nv_bfloat16* __restrict__ Ahi, const __nv_bfloat16* __restrict__ Alo,
    const __nv_bfloat16* __restrict__ Bhi, const __nv_bfloat16* __restrict__ Blo,
    float* __restrict__ C, int M, int N, int K)
{
    __shared__ __nv_bfloat16 sAhi[128 * LDA];
    __shared__ __nv_bfloat16 sAlo[128 * LDA];
    __shared__ __nv_bfloat16 sBhi[128 * LDA];
    __shared__ __nv_bfloat16 sBlo[128 * LDA];

    const int tid  = threadIdx.x;
    const int warp = tid >> 5;
    const int wr   = warp >> 2;       // 0..1
    const int wc   = warp & 3;        // 0..3
    const int by   = blockIdx.y * 128;
    const int bx   = blockIdx.x * 128;

    // global->smem load mapping: 4 threads per row, 8 bf16 each (16B)
    const int lr  = tid >> 2;         // 0..63 (two passes for 128 rows)
    const int lc8 = (tid & 3) * 8;

    wmma::fragment<wmma::accumulator, 16, 16, 16, float> acc[4][2];
#pragma unroll
    for (int i = 0; i < 4; ++i)
#pragma unroll
        for (int j = 0; j < 2; ++j) wmma::fill_fragment(acc[i][j], 0.0f);

    for (int k0 = 0; k0 < K; k0 += KC) {
        __syncthreads();
#pragma unroll
        for (int r = 0; r < 128; r += 64) {
            int row = lr + r;
            size_t ga = (size_t)(by + row) * K + k0 + lc8;
            size_t gb = (size_t)(bx + row) * K + k0 + lc8;
            *(uint4*)&sAhi[row * LDA + lc8] = *(const uint4*)&Ahi[ga];
            *(uint4*)&sAlo[row * LDA + lc8] = *(const uint4*)&Alo[ga];
            *(uint4*)&sBhi[row * LDA + lc8] = *(const uint4*)&Bhi[gb];
            *(uint4*)&sBlo[row * LDA + lc8] = *(const uint4*)&Blo[gb];
        }
        __syncthreads();

#pragma unroll
        for (int kk = 0; kk < KC; kk += 16) {
            wmma::fragment<wmma::matrix_a, 16, 16, 16, __nv_bfloat16, wmma::row_major> ahi[4], alo[4];
            wmma::fragment<wmma::matrix_b, 16, 16, 16, __nv_bfloat16, wmma::col_major> bhi[2], blo[2];
#pragma unroll
            for (int i = 0; i < 4; ++i) {
                int m0 = wr * 64 + i * 16;
                wmma::load_matrix_sync(ahi[i], &sAhi[m0 * LDA + kk], LDA);
                wmma::load_matrix_sync(alo[i], &sAlo[m0 * LDA + kk], LDA);
            }
#pragma unroll
            for (int j = 0; j < 2; ++j) {
                int n0 = wc * 32 + j * 16;
                wmma::load_matrix_sync(bhi[j], &sBhi[n0 * LDA + kk], LDA);
                wmma::load_matrix_sync(blo[j], &sBlo[n0 * LDA + kk], LDA);
            }
#pragma unroll
            for (int i = 0; i < 4; ++i)
#pragma unroll
                for (int j = 0; j < 2; ++j) {
                    wmma::mma_sync(acc[i][j], ahi[i], bhi[j], acc[i][j]);
                    wmma::mma_sync(acc[i][j], ahi[i], blo[j], acc[i][j]);
                    wmma::mma_sync(acc[i][j], alo[i], bhi[j], acc[i][j]);
                }
        }
    }

#pragma unroll
    for (int i = 0; i < 4; ++i)
#pragma unroll
        for (int j = 0; j < 2; ++j) {
            float* Cp = C + (size_t)(by + wr * 64 + i * 16) * N + bx + wc * 32 + j * 16;
            wmma::store_matrix_sync(Cp, acc[i][j], N, wmma::mem_row_major);
        }
}

// ---------------------------------------------------------------------------
// RoPE (in-place). t layout: [B, S, nh, HD]. half = HD/2 = 32.
// ---------------------------------------------------------------------------
__global__ void rope_kernel(float* __restrict__ t,
                            const float* __restrict__ cs,
                            const float* __restrict__ sn,
                            int nh, int total)
{
    int i = blockIdx.x * blockDim.x + threadIdx.x;
    if (i >= total) return;
    int d = i & 31;
    int g = i >> 5;
    int h = g % nh;
    int s = (g / nh) % S_;
    int b = g / (nh * S_);
    float c  = cs[s * 32 + d];
    float sv = sn[s * 32 + d];
    float* base = t + (((size_t)(b * S_ + s) * nh + h) * HD_);
    float x1 = base[d];
    float x2 = base[d + 32];
    base[d]      = x1 * c - x2 * sv;
    base[d + 32] = x2 * c + x1 * sv;
}

// ---------------------------------------------------------------------------
// Doc start scan
// ---------------------------------------------------------------------------
__global__ void docstart_kernel(const int* __restrict__ doc)
{
    int i = blockIdx.x * blockDim.x + threadIdx.x;
    if (i >= B_ * S_) return;
    int s = i & (S_ - 1);
    int d = doc[i];
    if (s == 0 || doc[i - 1] != d) g_dstart[(i >> 11) * 8 + d] = s;
}

// ---------------------------------------------------------------------------
// Flash attention (fp32), doc mask + causal, doc-start skipping.
// ---------------------------------------------------------------------------
__global__ __launch_bounds__(256) void flash_kernel(const int* __restrict__ doc,
                                                    float* __restrict__ ctx)
{
    extern __shared__ float sm[];
    float* Qs = sm;                  // 64*65
    float* Ks = Qs + 64 * 65;
    float* Vs = Ks + 64 * 65;
    float* Ps = Vs + 64 * 65;
    __shared__ int qdoc[64];
    __shared__ int kdoc[64];

    const int qb  = blockIdx.x;
    const int h   = blockIdx.y;
    const int b   = blockIdx.z;
    const int kvh = h >> 2;
    const int tid = threadIdx.x;
    const int tx  = tid & 15;
    const int ty  = tid >> 4;
    const int q0  = qb * 64;
    const int r0  = ty * 4;
    const int c0  = tx * 4;

    for (int idx = tid; idx < 64 * 64; idx += 256) {
        int r = idx >> 6, d = idx & 63;
        Qs[r * 65 + d] =
            g_q[(((size_t)(b * S_ + q0 + r)) * NH_ + h) * HD_ + d] * 0.125f;
    }
    if (tid < 64) qdoc[tid] = doc[b * S_ + q0 + tid];
    __syncthreads();

    const int kb0 = g_dstart[b * 8 + qdoc[0]] >> 6;

    float m[4], l[4], acc[4][4];
#pragma unroll
    for (int i = 0; i < 4; ++i) {
        m[i] = -1e30f;
        l[i] = 0.f;
#pragma unroll
        for (int j = 0; j < 4; ++j) acc[i][j] = 0.f;
    }

    for (int kb = kb0; kb <= qb; ++kb) {
        for (int idx = tid; idx < 64 * 64; idx += 256) {
            int r = idx >> 6, d = idx & 63;
            size_t g = (((size_t)(b * S_ + kb * 64 + r)) * NKV_ + kvh) * HD_ + d;
            Ks[r * 65 + d] = g_k[g];
            Vs[r * 65 + d] = g_v[g];
        }
        if (tid < 64) kdoc[tid] = doc[b * S_ + kb * 64 + tid];
        __syncthreads();

        float sc[4][4];
#pragma unroll
        for (int i = 0; i < 4; ++i)
#pragma unroll
            for (int j = 0; j < 4; ++j) sc[i][j] = 0.f;

#pragma unroll 8
        for (int d = 0; d < 64; ++d) {
            float qf[4], kf[4];
#pragma unroll
            for (int i = 0; i < 4; ++i) qf[i] = Qs[(r0 + i) * 65 + d];
#pragma unroll
            for (int j = 0; j < 4; ++j) kf[j] = Ks[(c0 + j) * 65 + d];
#pragma unroll
            for (int i = 0; i < 4; ++i)
#pragma unroll
                for (int j = 0; j < 4; ++j)
                    sc[i][j] = fmaf(qf[i], kf[j], sc[i][j]);
        }

#pragma unroll
        for (int i = 0; i < 4; ++i) {
            int qi = q0 + r0 + i;
            int qd = qdoc[r0 + i];
#pragma unroll
            for (int j = 0; j < 4; ++j) {
                int kj = kb * 64 + c0 + j;
                if (kj > qi || kdoc[c0 + j] != qd) sc[i][j] = -1e30f;
            }
        }

#pragma unroll
        for (int i = 0; i < 4; ++i) {
            float rm = sc[i][0];
            rm = fmaxf(rm, sc[i][1]);
            rm = fmaxf(rm, sc[i][2]);
            rm = fmaxf(rm, sc[i][3]);
#pragma unroll
            for (int off = 8; off; off >>= 1)
                rm = fmaxf(rm, __shfl_xor_sync(0xffffffffu, rm, off));
            float mn = fmaxf(m[i], rm);
            float corr = __expf(m[i] - mn);
            float rs = 0.f;
#pragma unroll
            for (int j = 0; j < 4; ++j) {
                sc[i][j] = __expf(sc[i][j] - mn);
                rs += sc[i][j];
            }
#pragma unroll
            for (int off = 8; off; off >>= 1)
                rs += __shfl_xor_sync(0xffffffffu, rs, off);
            l[i] = l[i] * corr + rs;
            m[i] = mn;
#pragma unroll
            for (int j = 0; j < 4; ++j) acc[i][j] *= corr;
        }

#pragma unroll
        for (int i = 0; i < 4; ++i)
#pragma unroll
            for (int j = 0; j < 4; ++j)
                Ps[(r0 + i) * 65 + c0 + j] = sc[i][j];
        __syncthreads();

#pragma unroll 8
        for (int c = 0; c < 64; ++c) {
            float pf[4], vf[4];
#pragma unroll
            for (int i = 0; i < 4; ++i) pf[i] = Ps[(r0 + i) * 65 + c];
#pragma unroll
            for (int j = 0; j < 4; ++j) vf[j] = Vs[c * 65 + c0 + j];
#pragma unroll
            for (int i = 0; i < 4; ++i)
#pragma unroll
                for (int j = 0; j < 4; ++j)
                    acc[i][j] = fmaf(pf[i], vf[j], acc[i][j]);
        }
        __syncthreads();
    }

#pragma unroll
    for (int i = 0; i < 4; ++i) {
        float inv = 1.0f / l[i];
        size_t base = (((size_t)(b * S_ + q0 + r0 + i)) * NH_ + h) * HD_ + c0;
#pragma unroll
        for (int j = 0; j < 4; ++j)
            ctx[base + j] = acc[i][j] * inv;
    }
}

// ---------------------------------------------------------------------------
// Host launcher
// ---------------------------------------------------------------------------
extern "C" void kernel_launch(void* const* d_in, const int* in_sizes, int n_in,
                              void* d_out, int out_size)
{
    const float* x   = (const float*)d_in[0];
    const float* rc  = (const float*)d_in[1];
    const float* rs  = (const float*)d_in[2];
    const int*   doc = (const int*)d_in[3];
    const float* Wq  = (const float*)d_in[4];
    const float* Wk  = (const float*)d_in[5];
    const float* Wv  = (const float*)d_in[6];
    const float* Wo  = (const float*)d_in[7];
    float* out = (float*)d_out;

    float *q_p, *k_p, *v_p, *ctx_p;
    cudaGetSymbolAddress((void**)&q_p,   g_q);
    cudaGetSymbolAddress((void**)&k_p,   g_k);
    cudaGetSymbolAddress((void**)&v_p,   g_v);
    cudaGetSymbolAddress((void**)&ctx_p, g_ctx);

    __nv_bfloat16 *xhi, *xlo, *wqhi, *wqlo, *wkhi, *wklo, *wvhi, *wvlo, *wohi, *wolo, *chi, *clo;
    cudaGetSymbolAddress((void**)&xhi, g_xhi);   cudaGetSymbolAddress((void**)&xlo, g_xlo);
    cudaGetSymbolAddress((void**)&wqhi, g_wqhi); cudaGetSymbolAddress((void**)&wqlo, g_wqlo);
    cudaGetSymbolAddress((void**)&wkhi, g_wkhi); cudaGetSymbolAddress((void**)&wklo, g_wklo);
    cudaGetSymbolAddress((void**)&wvhi, g_wvhi); cudaGetSymbolAddress((void**)&wvlo, g_wvlo);
    cudaGetSymbolAddress((void**)&wohi, g_wohi); cudaGetSymbolAddress((void**)&wolo, g_wolo);
    cudaGetSymbolAddress((void**)&chi, g_chi);   cudaGetSymbolAddress((void**)&clo, g_clo);

    const int flash_smem = 4 * 64 * 65 * (int)sizeof(float);
    cudaFuncSetAttribute(flash_kernel,
                         cudaFuncAttributeMaxDynamicSharedMemorySize,
                         flash_smem);

    // Split inputs to bf16 hi/lo
    {
        int n;
        n = M_ * DIM_;    split_kernel<<<(n + 255) / 256, 256>>>(x,  xhi,  xlo,  n);
        n = DIM_ * DIM_;  split_kernel<<<(n + 255) / 256, 256>>>(Wq, wqhi, wqlo, n);
        n = 512 * DIM_;   split_kernel<<<(n + 255) / 256, 256>>>(Wk, wkhi, wklo, n);
        n = 512 * DIM_;   split_kernel<<<(n + 255) / 256, 256>>>(Wv, wvhi, wvlo, n);
        n = DIM_ * DIM_;  split_kernel<<<(n + 255) / 256, 256>>>(Wo, wohi, wolo, n);
    }

    // QKV projections (tensor core bf16-split)
    {
        dim3 gq(NH_ * HD_ / 128, M_ / 128);   // (16, 32)
        gemm_bf16split<<<gq, 256>>>(xhi, xlo, wqhi, wqlo, q_p, M_, NH_ * HD_, DIM_);
        dim3 gk(512 / 128, M_ / 128);         // (4, 32)
        gemm_bf16split<<<gk, 256>>>(xhi, xlo, wkhi, wklo, k_p, M_, 512, DIM_);
        gemm_bf16split<<<gk, 256>>>(xhi, xlo, wvhi, wvlo, v_p, M_, 512, DIM_);
    }

    // RoPE on Q and K
    {
        int tq = B_ * S_ * NH_ * 32;
        rope_kernel<<<(tq + 255) / 256, 256>>>(q_p, rc, rs, NH_, tq);
        int tk = B_ * S_ * NKV_ * 32;
        rope_kernel<<<(tk + 255) / 256, 256>>>(k_p, rc, rs, NKV_, tk);
    }

    // doc start offsets
    docstart_kernel<<<(B_ * S_ + 255) / 256, 256>>>(doc);

    // flash attention
    {
        dim3 g(S_ / 64, NH_, B_);
        flash_kernel<<<g, 256, flash_smem>>>(doc, ctx_p);
    }

    // split ctx, then output projection
    {
        int n = M_ * DIM_;
        split_kernel<<<(n + 255) / 256, 256>>>(ctx_p, chi, clo, n);
        dim3 go(DIM_ / 128, M_ / 128);
        gemm_bf16split<<<go, 256>>>(chi, clo, wohi, wolo, out, M_, DIM_, DIM_);
    }
}

// round 4
// speedup vs baseline: 2.3425x; 1.3705x over previous
#include <cuda_runtime.h>
#include <cuda_bf16.h>
#include <mma.h>
#include <math.h>
#include <stdint.h>

using namespace nvcuda;

// Problem constants
#define B_    2
#define S_    2048
#define DIM_  2048
#define NH_   32
#define NKV_  8
#define HD_   64
#define M_    (B_ * S_)        // 4096 rows

// ---------------------------------------------------------------------------
// Scratch (static device globals — no allocation allowed)
// ---------------------------------------------------------------------------
__device__ float g_q[M_ * NH_ * HD_];
__device__ float g_k[M_ * NKV_ * HD_];
__device__ float g_v[M_ * NKV_ * HD_];
__device__ float g_ctx[M_ * NH_ * HD_];
__device__ int   g_dstart[B_ * 8];

// bf16 hi/lo split copies
__device__ __nv_bfloat16 g_xhi[M_ * DIM_],   g_xlo[M_ * DIM_];
__device__ __nv_bfloat16 g_wqhi[DIM_ * DIM_], g_wqlo[DIM_ * DIM_];
__device__ __nv_bfloat16 g_wkhi[512 * DIM_],  g_wklo[512 * DIM_];
__device__ __nv_bfloat16 g_wvhi[512 * DIM_],  g_wvlo[512 * DIM_];
__device__ __nv_bfloat16 g_wohi[DIM_ * DIM_], g_wolo[DIM_ * DIM_];
__device__ __nv_bfloat16 g_chi[M_ * DIM_],   g_clo[M_ * DIM_];

// ---------------------------------------------------------------------------
// cp.async helpers
// ---------------------------------------------------------------------------
__device__ __forceinline__ uint32_t smem_u32(const void* p) {
    uint32_t a;
    asm("{ .reg .u64 t; cvta.to.shared.u64 t, %1; cvt.u32.u64 %0, t; }"
        : "=r"(a) : "l"(p));
    return a;
}
__device__ __forceinline__ void cp16(uint32_t dst, const void* src) {
    asm volatile("cp.async.cg.shared.global [%0], [%1], 16;"
                 :: "r"(dst), "l"(src));
}
__device__ __forceinline__ void cp_commit() {
    asm volatile("cp.async.commit_group;");
}
template<int N>
__device__ __forceinline__ void cp_wait() {
    asm volatile("cp.async.wait_group %0;" :: "n"(N));
}

// ---------------------------------------------------------------------------
// fp32 -> bf16 hi + residual lo  (vectorized x4)
// ---------------------------------------------------------------------------
__global__ void split_kernel(const float* __restrict__ src,
                             __nv_bfloat16* __restrict__ hi,
                             __nv_bfloat16* __restrict__ lo, int n4)
{
    int i = blockIdx.x * blockDim.x + threadIdx.x;
    if (i >= n4) return;
    float4 v = ((const float4*)src)[i];
    __nv_bfloat16 h0 = __float2bfloat16(v.x);
    __nv_bfloat16 h1 = __float2bfloat16(v.y);
    __nv_bfloat16 h2 = __float2bfloat16(v.z);
    __nv_bfloat16 h3 = __float2bfloat16(v.w);
    __nv_bfloat162 hh0 = {h0, h1}, hh1 = {h2, h3};
    ((__nv_bfloat162*)hi)[i * 2]     = hh0;
    ((__nv_bfloat162*)hi)[i * 2 + 1] = hh1;
    __nv_bfloat162 ll0 = {__float2bfloat16(v.x - __bfloat162float(h0)),
                          __float2bfloat16(v.y - __bfloat162float(h1))};
    __nv_bfloat162 ll1 = {__float2bfloat16(v.z - __bfloat162float(h2)),
                          __float2bfloat16(v.w - __bfloat162float(h3))};
    ((__nv_bfloat162*)lo)[i * 2]     = ll0;
    ((__nv_bfloat162*)lo)[i * 2 + 1] = ll1;
}

// ---------------------------------------------------------------------------
// bf16-split GEMM: C[M,N] = A[M,K] * B[N,K]^T  (fp32 accumulate)
// 128x128 tile, KC=32, 8 warps (2x4), warp tile 64x32.
// cp.async double-buffered pipeline.
// C = Ahi*Bhi + Ahi*Blo + Alo*Bhi   (error ~2^-16)
// ---------------------------------------------------------------------------
#define KC  32
#define LDA 40   // padded leading dim in smem (bf16 elems); 80B row = 5*16B

__global__ __launch_bounds__(256, 2) void gemm_bf16split(
    const __nv_bfloat16* __restrict__ Ahi, const __nv_bfloat16* __restrict__ Alo,
    const __nv_bfloat16* __restrict__ Bhi, const __nv_bfloat16* __restrict__ Blo,
    float* __restrict__ C, int M, int N, int K)
{
    // 4 logical tiles (Ahi|Alo|Bhi|Blo) x 2 stages, each 128 x LDA bf16
    __shared__ __nv_bfloat16 smem[2][4][128 * LDA];

    const int tid  = threadIdx.x;
    const int warp = tid >> 5;
    const int wr   = warp >> 2;       // 0..1
    const int wc   = warp & 3;        // 0..3
    const int by   = blockIdx.y * 128;
    const int bx   = blockIdx.x * 128;

    // load mapping: 4 threads per row, 8 bf16 (16B) each; 64 rows per pass
    const int lr  = tid >> 2;         // 0..63
    const int lc8 = (tid & 3) * 8;    // 0,8,16,24

    const __nv_bfloat16* gp[4];
    gp[0] = Ahi + (size_t)(by + lr) * K + lc8;
    gp[1] = Alo + (size_t)(by + lr) * K + lc8;
    gp[2] = Bhi + (size_t)(bx + lr) * K + lc8;
    gp[3] = Blo + (size_t)(bx + lr) * K + lc8;

    uint32_t sp[4];
#pragma unroll
    for (int t = 0; t < 4; ++t)
        sp[t] = smem_u32(&smem[0][t][lr * LDA + lc8]);
    const uint32_t stage_b = (uint32_t)(4 * 128 * LDA * 2);  // bytes per stage
    const uint32_t half_b  = (uint32_t)(64 * LDA * 2);       // 64 rows

    auto load_stage = [&](int it, int buf) {
        int k0 = it * KC;
#pragma unroll
        for (int t = 0; t < 4; ++t) {
            cp16(sp[t] + buf * stage_b,          gp[t] + k0);
            cp16(sp[t] + buf * stage_b + half_b, gp[t] + (size_t)64 * K + k0);
        }
        cp_commit();
    };

    wmma::fragment<wmma::accumulator, 16, 16, 16, float> acc[4][2];
#pragma unroll
    for (int i = 0; i < 4; ++i)
#pragma unroll
        for (int j = 0; j < 2; ++j) wmma::fill_fragment(acc[i][j], 0.0f);

    const int NIT = K / KC;
    load_stage(0, 0);

    for (int it = 0; it < NIT; ++it) {
        int buf = it & 1;
        if (it + 1 < NIT) {
            load_stage(it + 1, buf ^ 1);
            cp_wait<1>();
        } else {
            cp_wait<0>();
        }
        __syncthreads();

        const __nv_bfloat16* sa_hi = smem[buf][0];
        const __nv_bfloat16* sa_lo = smem[buf][1];
        const __nv_bfloat16* sb_hi = smem[buf][2];
        const __nv_bfloat16* sb_lo = smem[buf][3];

#pragma unroll
        for (int kk = 0; kk < KC; kk += 16) {
            wmma::fragment<wmma::matrix_a, 16, 16, 16, __nv_bfloat16, wmma::row_major> ahi[4], alo[4];
            wmma::fragment<wmma::matrix_b, 16, 16, 16, __nv_bfloat16, wmma::col_major> bhi[2], blo[2];
#pragma unroll
            for (int i = 0; i < 4; ++i) {
                int m0 = wr * 64 + i * 16;
                wmma::load_matrix_sync(ahi[i], &sa_hi[m0 * LDA + kk], LDA);
                wmma::load_matrix_sync(alo[i], &sa_lo[m0 * LDA + kk], LDA);
            }
#pragma unroll
            for (int j = 0; j < 2; ++j) {
                int n0 = wc * 32 + j * 16;
                wmma::load_matrix_sync(bhi[j], &sb_hi[n0 * LDA + kk], LDA);
                wmma::load_matrix_sync(blo[j], &sb_lo[n0 * LDA + kk], LDA);
            }
#pragma unroll
            for (int i = 0; i < 4; ++i)
#pragma unroll
                for (int j = 0; j < 2; ++j) {
                    wmma::mma_sync(acc[i][j], ahi[i], bhi[j], acc[i][j]);
                    wmma::mma_sync(acc[i][j], ahi[i], blo[j], acc[i][j]);
                    wmma::mma_sync(acc[i][j], alo[i], bhi[j], acc[i][j]);
                }
        }
        __syncthreads();
    }

#pragma unroll
    for (int i = 0; i < 4; ++i)
#pragma unroll
        for (int j = 0; j < 2; ++j) {
            float* Cp = C + (size_t)(by + wr * 64 + i * 16) * N + bx + wc * 32 + j * 16;
            wmma::store_matrix_sync(Cp, acc[i][j], N, wmma::mem_row_major);
        }
}

// ---------------------------------------------------------------------------
// RoPE (in-place). t layout: [B, S, nh, HD]. half = HD/2 = 32.
// ---------------------------------------------------------------------------
__global__ void rope_kernel(float* __restrict__ t,
                            const float* __restrict__ cs,
                            const float* __restrict__ sn,
                            int nh, int total)
{
    int i = blockIdx.x * blockDim.x + threadIdx.x;
    if (i >= total) return;
    int d = i & 31;
    int g = i >> 5;
    int h = g % nh;
    int s = (g / nh) % S_;
    int b = g / (nh * S_);
    float c  = cs[s * 32 + d];
    float sv = sn[s * 32 + d];
    float* base = t + (((size_t)(b * S_ + s) * nh + h) * HD_);
    float x1 = base[d];
    float x2 = base[d + 32];
    base[d]      = x1 * c - x2 * sv;
    base[d + 32] = x2 * c + x1 * sv;
}

// ---------------------------------------------------------------------------
// Doc start scan
// ---------------------------------------------------------------------------
__global__ void docstart_kernel(const int* __restrict__ doc)
{
    int i = blockIdx.x * blockDim.x + threadIdx.x;
    if (i >= B_ * S_) return;
    int s = i & (S_ - 1);
    int d = doc[i];
    if (s == 0 || doc[i - 1] != d) g_dstart[(i >> 11) * 8 + d] = s;
}

// ---------------------------------------------------------------------------
// Flash attention (fp32), doc mask + causal, doc-start skipping.
// ---------------------------------------------------------------------------
__global__ __launch_bounds__(256) void flash_kernel(const int* __restrict__ doc,
                                                    float* __restrict__ ctx)
{
    extern __shared__ float sm[];
    float* Qs = sm;
    float* Ks = Qs + 64 * 65;
    float* Vs = Ks + 64 * 65;
    float* Ps = Vs + 64 * 65;
    __shared__ int qdoc[64];
    __shared__ int kdoc[64];

    const int qb  = blockIdx.x;
    const int h   = blockIdx.y;
    const int b   = blockIdx.z;
    const int kvh = h >> 2;
    const int tid = threadIdx.x;
    const int tx  = tid & 15;
    const int ty  = tid >> 4;
    const int q0  = qb * 64;
    const int r0  = ty * 4;
    const int c0  = tx * 4;

    for (int idx = tid; idx < 64 * 64; idx += 256) {
        int r = idx >> 6, d = idx & 63;
        Qs[r * 65 + d] =
            g_q[(((size_t)(b * S_ + q0 + r)) * NH_ + h) * HD_ + d] * 0.125f;
    }
    if (tid < 64) qdoc[tid] = doc[b * S_ + q0 + tid];
    __syncthreads();

    const int kb0 = g_dstart[b * 8 + qdoc[0]] >> 6;

    float m[4], l[4], acc[4][4];
#pragma unroll
    for (int i = 0; i < 4; ++i) {
        m[i] = -1e30f; l[i] = 0.f;
#pragma unroll
        for (int j = 0; j < 4; ++j) acc[i][j] = 0.f;
    }

    for (int kb = kb0; kb <= qb; ++kb) {
        for (int idx = tid; idx < 64 * 64; idx += 256) {
            int r = idx >> 6, d = idx & 63;
            size_t g = (((size_t)(b * S_ + kb * 64 + r)) * NKV_ + kvh) * HD_ + d;
            Ks[r * 65 + d] = g_k[g];
            Vs[r * 65 + d] = g_v[g];
        }
        if (tid < 64) kdoc[tid] = doc[b * S_ + kb * 64 + tid];
        __syncthreads();

        float sc[4][4];
#pragma unroll
        for (int i = 0; i < 4; ++i)
#pragma unroll
            for (int j = 0; j < 4; ++j) sc[i][j] = 0.f;

#pragma unroll 8
        for (int d = 0; d < 64; ++d) {
            float qf[4], kf[4];
#pragma unroll
            for (int i = 0; i < 4; ++i) qf[i] = Qs[(r0 + i) * 65 + d];
#pragma unroll
            for (int j = 0; j < 4; ++j) kf[j] = Ks[(c0 + j) * 65 + d];
#pragma unroll
            for (int i = 0; i < 4; ++i)
#pragma unroll
                for (int j = 0; j < 4; ++j)
                    sc[i][j] = fmaf(qf[i], kf[j], sc[i][j]);
        }

#pragma unroll
        for (int i = 0; i < 4; ++i) {
            int qi = q0 + r0 + i;
            int qd = qdoc[r0 + i];
#pragma unroll
            for (int j = 0; j < 4; ++j) {
                int kj = kb * 64 + c0 + j;
                if (kj > qi || kdoc[c0 + j] != qd) sc[i][j] = -1e30f;
            }
        }

#pragma unroll
        for (int i = 0; i < 4; ++i) {
            float rm = sc[i][0];
            rm = fmaxf(rm, sc[i][1]);
            rm = fmaxf(rm, sc[i][2]);
            rm = fmaxf(rm, sc[i][3]);
#pragma unroll
            for (int off = 8; off; off >>= 1)
                rm = fmaxf(rm, __shfl_xor_sync(0xffffffffu, rm, off));
            float mn = fmaxf(m[i], rm);
            float corr = __expf(m[i] - mn);
            float rs = 0.f;
#pragma unroll
            for (int j = 0; j < 4; ++j) {
                sc[i][j] = __expf(sc[i][j] - mn);
                rs += sc[i][j];
            }
#pragma unroll
            for (int off = 8; off; off >>= 1)
                rs += __shfl_xor_sync(0xffffffffu, rs, off);
            l[i] = l[i] * corr + rs;
            m[i] = mn;
#pragma unroll
            for (int j = 0; j < 4; ++j) acc[i][j] *= corr;
        }

#pragma unroll
        for (int i = 0; i < 4; ++i)
#pragma unroll
            for (int j = 0; j < 4; ++j)
                Ps[(r0 + i) * 65 + c0 + j] = sc[i][j];
        __syncthreads();

#pragma unroll 8
        for (int c = 0; c < 64; ++c) {
            float pf[4], vf[4];
#pragma unroll
            for (int i = 0; i < 4; ++i) pf[i] = Ps[(r0 + i) * 65 + c];
#pragma unroll
            for (int j = 0; j < 4; ++j) vf[j] = Vs[c * 65 + c0 + j];
#pragma unroll
            for (int i = 0; i < 4; ++i)
#pragma unroll
                for (int j = 0; j < 4; ++j)
                    acc[i][j] = fmaf(pf[i], vf[j], acc[i][j]);
        }
        __syncthreads();
    }

#pragma unroll
    for (int i = 0; i < 4; ++i) {
        float inv = 1.0f / l[i];
        size_t base = (((size_t)(b * S_ + q0 + r0 + i)) * NH_ + h) * HD_ + c0;
#pragma unroll
        for (int j = 0; j < 4; ++j)
            ctx[base + j] = acc[i][j] * inv;
    }
}

// ---------------------------------------------------------------------------
// Host launcher
// ---------------------------------------------------------------------------
extern "C" void kernel_launch(void* const* d_in, const int* in_sizes, int n_in,
                              void* d_out, int out_size)
{
    const float* x   = (const float*)d_in[0];
    const float* rc  = (const float*)d_in[1];
    const float* rs  = (const float*)d_in[2];
    const int*   doc = (const int*)d_in[3];
    const float* Wq  = (const float*)d_in[4];
    const float* Wk  = (const float*)d_in[5];
    const float* Wv  = (const float*)d_in[6];
    const float* Wo  = (const float*)d_in[7];
    float* out = (float*)d_out;

    float *q_p, *k_p, *v_p, *ctx_p;
    cudaGetSymbolAddress((void**)&q_p,   g_q);
    cudaGetSymbolAddress((void**)&k_p,   g_k);
    cudaGetSymbolAddress((void**)&v_p,   g_v);
    cudaGetSymbolAddress((void**)&ctx_p, g_ctx);

    __nv_bfloat16 *xhi, *xlo, *wqhi, *wqlo, *wkhi, *wklo, *wvhi, *wvlo,
                  *wohi, *wolo, *chi, *clo;
    cudaGetSymbolAddress((void**)&xhi, g_xhi);   cudaGetSymbolAddress((void**)&xlo, g_xlo);
    cudaGetSymbolAddress((void**)&wqhi, g_wqhi); cudaGetSymbolAddress((void**)&wqlo, g_wqlo);
    cudaGetSymbolAddress((void**)&wkhi, g_wkhi); cudaGetSymbolAddress((void**)&wklo, g_wklo);
    cudaGetSymbolAddress((void**)&wvhi, g_wvhi); cudaGetSymbolAddress((void**)&wvlo, g_wvlo);
    cudaGetSymbolAddress((void**)&wohi, g_wohi); cudaGetSymbolAddress((void**)&wolo, g_wolo);
    cudaGetSymbolAddress((void**)&chi, g_chi);   cudaGetSymbolAddress((void**)&clo, g_clo);

    const int flash_smem = 4 * 64 * 65 * (int)sizeof(float);
    cudaFuncSetAttribute(flash_kernel,
                         cudaFuncAttributeMaxDynamicSharedMemorySize, flash_smem);

    // Split inputs to bf16 hi/lo
    {
        int n4;
        n4 = M_ * DIM_ / 4;    split_kernel<<<(n4 + 255) / 256, 256>>>(x,  xhi,  xlo,  n4);
        n4 = DIM_ * DIM_ / 4;  split_kernel<<<(n4 + 255) / 256, 256>>>(Wq, wqhi, wqlo, n4);
        n4 = 512 * DIM_ / 4;   split_kernel<<<(n4 + 255) / 256, 256>>>(Wk, wkhi, wklo, n4);
        n4 = 512 * DIM_ / 4;   split_kernel<<<(n4 + 255) / 256, 256>>>(Wv, wvhi, wvlo, n4);
        n4 = DIM_ * DIM_ / 4;  split_kernel<<<(n4 + 255) / 256, 256>>>(Wo, wohi, wolo, n4);
    }

    // QKV projections (tensor core bf16-split, cp.async pipelined)
    {
        dim3 gq(NH_ * HD_ / 128, M_ / 128);   // (16, 32)
        gemm_bf16split<<<gq, 256>>>(xhi, xlo, wqhi, wqlo, q_p, M_, NH_ * HD_, DIM_);
        dim3 gk(512 / 128, M_ / 128);         // (4, 32)
        gemm_bf16split<<<gk, 256>>>(xhi, xlo, wkhi, wklo, k_p, M_, 512, DIM_);
        gemm_bf16split<<<gk, 256>>>(xhi, xlo, wvhi, wvlo, v_p, M_, 512, DIM_);
    }

    // RoPE on Q and K
    {
        int tq = B_ * S_ * NH_ * 32;
        rope_kernel<<<(tq + 255) / 256, 256>>>(q_p, rc, rs, NH_, tq);
        int tk = B_ * S_ * NKV_ * 32;
        rope_kernel<<<(tk + 255) / 256, 256>>>(k_p, rc, rs, NKV_, tk);
    }

    // doc start offsets
    docstart_kernel<<<(B_ * S_ + 255) / 256, 256>>>(doc);

    // flash attention
    {
        dim3 g(S_ / 64, NH_, B_);
        flash_kernel<<<g, 256, flash_smem>>>(doc, ctx_p);
    }

    // split ctx, then output projection
    {
        int n4 = M_ * DIM_ / 4;
        split_kernel<<<(n4 + 255) / 256, 256>>>(ctx_p, chi, clo, n4);
        dim3 go(DIM_ / 128, M_ / 128);
        gemm_bf16split<<<go, 256>>>(chi, clo, wohi, wolo, out, M_, DIM_, DIM_);
    }
}

// round 5
// speedup vs baseline: 2.6929x; 1.1496x over previous
#include <cuda_runtime.h>
#include <cuda_bf16.h>
#include <mma.h>
#include <math.h>
#include <stdint.h>
#include <string.h>

using namespace nvcuda;

// Problem constants
#define B_    2
#define S_    2048
#define DIM_  2048
#define NH_   32
#define NKV_  8
#define HD_   64
#define M_    (B_ * S_)        // 4096 rows

// ---------------------------------------------------------------------------
// Scratch (static device globals — no allocation allowed)
// ---------------------------------------------------------------------------
__device__ float g_q[M_ * NH_ * HD_];
__device__ float g_k[M_ * NKV_ * HD_];
__device__ float g_v[M_ * NKV_ * HD_];
__device__ int   g_dstart[B_ * 8];

// bf16 hi/lo split copies (GEMM inputs)
__device__ __nv_bfloat16 g_xhi[M_ * DIM_],    g_xlo[M_ * DIM_];
__device__ __nv_bfloat16 g_wqhi[DIM_ * DIM_], g_wqlo[DIM_ * DIM_];
__device__ __nv_bfloat16 g_wkhi[512 * DIM_],  g_wklo[512 * DIM_];
__device__ __nv_bfloat16 g_wvhi[512 * DIM_],  g_wvlo[512 * DIM_];
__device__ __nv_bfloat16 g_wohi[DIM_ * DIM_], g_wolo[DIM_ * DIM_];
__device__ __nv_bfloat16 g_chi[M_ * DIM_],    g_clo[M_ * DIM_];
// flash inputs (post-rope, bf16 hi/lo)
__device__ __nv_bfloat16 g_qbh[M_ * 2048], g_qbl[M_ * 2048];
__device__ __nv_bfloat16 g_kbh[M_ * 512],  g_kbl[M_ * 512];
__device__ __nv_bfloat16 g_vbh[M_ * 512],  g_vbl[M_ * 512];

// ---------------------------------------------------------------------------
// PTX helpers
// ---------------------------------------------------------------------------
__device__ __forceinline__ uint32_t smem_u32(const void* p) {
    uint32_t a;
    asm("{ .reg .u64 t; cvta.to.shared.u64 t, %1; cvt.u32.u64 %0, t; }"
        : "=r"(a) : "l"(p));
    return a;
}
__device__ __forceinline__ void cp16(uint32_t dst, const void* src) {
    asm volatile("cp.async.cg.shared.global [%0], [%1], 16;"
                 :: "r"(dst), "l"(src));
}
__device__ __forceinline__ void cp_commit() {
    asm volatile("cp.async.commit_group;");
}
template<int N>
__device__ __forceinline__ void cp_wait() {
    asm volatile("cp.async.wait_group %0;" :: "n"(N));
}
__device__ __forceinline__ void ldm4(uint32_t* r, uint32_t a) {
    asm volatile("ldmatrix.sync.aligned.m8n8.x4.shared.b16 {%0,%1,%2,%3}, [%4];"
        : "=r"(r[0]), "=r"(r[1]), "=r"(r[2]), "=r"(r[3]) : "r"(a));
}
__device__ __forceinline__ void ldm4t(uint32_t* r, uint32_t a) {
    asm volatile("ldmatrix.sync.aligned.m8n8.x4.trans.shared.b16 {%0,%1,%2,%3}, [%4];"
        : "=r"(r[0]), "=r"(r[1]), "=r"(r[2]), "=r"(r[3]) : "r"(a));
}
__device__ __forceinline__ void mma16816(float* c, const uint32_t* a,
                                         uint32_t b0, uint32_t b1) {
    asm volatile(
        "mma.sync.aligned.m16n8k16.row.col.f32.bf16.bf16.f32 "
        "{%0,%1,%2,%3}, {%4,%5,%6,%7}, {%8,%9}, {%0,%1,%2,%3};"
        : "+f"(c[0]), "+f"(c[1]), "+f"(c[2]), "+f"(c[3])
        : "r"(a[0]), "r"(a[1]), "r"(a[2]), "r"(a[3]), "r"(b0), "r"(b1));
}
union BF2U { __nv_bfloat162 b; uint32_t u; };
__device__ __forceinline__ uint32_t packsplit(float x, float y, uint32_t& lo) {
    __nv_bfloat16 hx = __float2bfloat16(x), hy = __float2bfloat16(y);
    BF2U H, L;
    H.b.x = hx; H.b.y = hy;
    L.b.x = __float2bfloat16(x - __bfloat162float(hx));
    L.b.y = __float2bfloat16(y - __bfloat162float(hy));
    lo = L.u;
    return H.u;
}

// ---------------------------------------------------------------------------
// fp32 -> bf16 hi + residual lo  (vectorized x4)
// ---------------------------------------------------------------------------
__global__ void split_kernel(const float* __restrict__ src,
                             __nv_bfloat16* __restrict__ hi,
                             __nv_bfloat16* __restrict__ lo, int n4)
{
    int i = blockIdx.x * blockDim.x + threadIdx.x;
    if (i >= n4) return;
    float4 v = ((const float4*)src)[i];
    __nv_bfloat16 h0 = __float2bfloat16(v.x);
    __nv_bfloat16 h1 = __float2bfloat16(v.y);
    __nv_bfloat16 h2 = __float2bfloat16(v.z);
    __nv_bfloat16 h3 = __float2bfloat16(v.w);
    __nv_bfloat162 hh0 = {h0, h1}, hh1 = {h2, h3};
    ((__nv_bfloat162*)hi)[i * 2]     = hh0;
    ((__nv_bfloat162*)hi)[i * 2 + 1] = hh1;
    __nv_bfloat162 ll0 = {__float2bfloat16(v.x - __bfloat162float(h0)),
                          __float2bfloat16(v.y - __bfloat162float(h1))};
    __nv_bfloat162 ll1 = {__float2bfloat16(v.z - __bfloat162float(h2)),
                          __float2bfloat16(v.w - __bfloat162float(h3))};
    ((__nv_bfloat162*)lo)[i * 2]     = ll0;
    ((__nv_bfloat162*)lo)[i * 2 + 1] = ll1;
}

// ---------------------------------------------------------------------------
// bf16-split GEMM (as R4): C = A*B^T, 128x128 tile, cp.async double buffer
// ---------------------------------------------------------------------------
#define KC  32
#define LDA 40

__global__ __launch_bounds__(256, 2) void gemm_bf16split(
    const __nv_bfloat16* __restrict__ Ahi, const __nv_bfloat16* __restrict__ Alo,
    const __nv_bfloat16* __restrict__ Bhi, const __nv_bfloat16* __restrict__ Blo,
    float* __restrict__ C, int M, int N, int K)
{
    __shared__ __nv_bfloat16 smem[2][4][128 * LDA];

    const int tid  = threadIdx.x;
    const int warp = tid >> 5;
    const int wr   = warp >> 2;
    const int wc   = warp & 3;
    const int by   = blockIdx.y * 128;
    const int bx   = blockIdx.x * 128;

    const int lr  = tid >> 2;
    const int lc8 = (tid & 3) * 8;

    const __nv_bfloat16* gp[4];
    gp[0] = Ahi + (size_t)(by + lr) * K + lc8;
    gp[1] = Alo + (size_t)(by + lr) * K + lc8;
    gp[2] = Bhi + (size_t)(bx + lr) * K + lc8;
    gp[3] = Blo + (size_t)(bx + lr) * K + lc8;

    uint32_t sp[4];
#pragma unroll
    for (int t = 0; t < 4; ++t)
        sp[t] = smem_u32(&smem[0][t][lr * LDA + lc8]);
    const uint32_t stage_b = (uint32_t)(4 * 128 * LDA * 2);
    const uint32_t half_b  = (uint32_t)(64 * LDA * 2);

    auto load_stage = [&](int it, int buf) {
        int k0 = it * KC;
#pragma unroll
        for (int t = 0; t < 4; ++t) {
            cp16(sp[t] + buf * stage_b,          gp[t] + k0);
            cp16(sp[t] + buf * stage_b + half_b, gp[t] + (size_t)64 * K + k0);
        }
        cp_commit();
    };

    wmma::fragment<wmma::accumulator, 16, 16, 16, float> acc[4][2];
#pragma unroll
    for (int i = 0; i < 4; ++i)
#pragma unroll
        for (int j = 0; j < 2; ++j) wmma::fill_fragment(acc[i][j], 0.0f);

    const int NIT = K / KC;
    load_stage(0, 0);

    for (int it = 0; it < NIT; ++it) {
        int buf = it & 1;
        if (it + 1 < NIT) {
            load_stage(it + 1, buf ^ 1);
            cp_wait<1>();
        } else {
            cp_wait<0>();
        }
        __syncthreads();

        const __nv_bfloat16* sa_hi = smem[buf][0];
        const __nv_bfloat16* sa_lo = smem[buf][1];
        const __nv_bfloat16* sb_hi = smem[buf][2];
        const __nv_bfloat16* sb_lo = smem[buf][3];

#pragma unroll
        for (int kk = 0; kk < KC; kk += 16) {
            wmma::fragment<wmma::matrix_a, 16, 16, 16, __nv_bfloat16, wmma::row_major> ahi[4], alo[4];
            wmma::fragment<wmma::matrix_b, 16, 16, 16, __nv_bfloat16, wmma::col_major> bhi[2], blo[2];
#pragma unroll
            for (int i = 0; i < 4; ++i) {
                int m0 = wr * 64 + i * 16;
                wmma::load_matrix_sync(ahi[i], &sa_hi[m0 * LDA + kk], LDA);
                wmma::load_matrix_sync(alo[i], &sa_lo[m0 * LDA + kk], LDA);
            }
#pragma unroll
            for (int j = 0; j < 2; ++j) {
                int n0 = wc * 32 + j * 16;
                wmma::load_matrix_sync(bhi[j], &sb_hi[n0 * LDA + kk], LDA);
                wmma::load_matrix_sync(blo[j], &sb_lo[n0 * LDA + kk], LDA);
            }
#pragma unroll
            for (int i = 0; i < 4; ++i)
#pragma unroll
                for (int j = 0; j < 2; ++j) {
                    wmma::mma_sync(acc[i][j], ahi[i], bhi[j], acc[i][j]);
                    wmma::mma_sync(acc[i][j], ahi[i], blo[j], acc[i][j]);
                    wmma::mma_sync(acc[i][j], alo[i], bhi[j], acc[i][j]);
                }
        }
        __syncthreads();
    }

#pragma unroll
    for (int i = 0; i < 4; ++i)
#pragma unroll
        for (int j = 0; j < 2; ++j) {
            float* Cp = C + (size_t)(by + wr * 64 + i * 16) * N + bx + wc * 32 + j * 16;
            wmma::store_matrix_sync(Cp, acc[i][j], N, wmma::mem_row_major);
        }
}

// ---------------------------------------------------------------------------
// RoPE + bf16 hi/lo split (reads fp32 proj, writes split bf16, scaled)
// ---------------------------------------------------------------------------
__global__ void rope_split_kernel(const float* __restrict__ t,
                                  const float* __restrict__ cs,
                                  const float* __restrict__ sn,
                                  __nv_bfloat16* __restrict__ hi,
                                  __nv_bfloat16* __restrict__ lo,
                                  int nh, int total, float scale)
{
    int i = blockIdx.x * blockDim.x + threadIdx.x;
    if (i >= total) return;
    int d = i & 31;
    int g = i >> 5;
    int h = g % nh;
    int s = (g / nh) % S_;
    int b = g / (nh * S_);
    float c  = cs[s * 32 + d];
    float sv = sn[s * 32 + d];
    size_t o = ((size_t)(b * S_ + s) * nh + h) * HD_;
    float x1 = t[o + d];
    float x2 = t[o + d + 32];
    float y1 = (x1 * c - x2 * sv) * scale;
    float y2 = (x2 * c + x1 * sv) * scale;
    __nv_bfloat16 h1 = __float2bfloat16(y1), h2 = __float2bfloat16(y2);
    hi[o + d]      = h1;
    hi[o + d + 32] = h2;
    lo[o + d]      = __float2bfloat16(y1 - __bfloat162float(h1));
    lo[o + d + 32] = __float2bfloat16(y2 - __bfloat162float(h2));
}

// ---------------------------------------------------------------------------
// Doc start scan
// ---------------------------------------------------------------------------
__global__ void docstart_kernel(const int* __restrict__ doc)
{
    int i = blockIdx.x * blockDim.x + threadIdx.x;
    if (i >= B_ * S_) return;
    int s = i & (S_ - 1);
    int d = doc[i];
    if (s == 0 || doc[i - 1] != d) g_dstart[(i >> 11) * 8 + d] = s;
}

// ---------------------------------------------------------------------------
// Tensor-core flash attention. 64q x 64k tile, 128 threads (4 warps x 16 rows).
// mma.sync m16n8k16 bf16, 3-pass hi/lo split for QK^T and PV.
// Writes ctx directly as bf16 hi/lo.
// ---------------------------------------------------------------------------
#define LDK 72   // smem row pitch (bf16 elems), 144B rows

__global__ __launch_bounds__(128) void flash_tc(
    const int* __restrict__ doc,
    const __nv_bfloat16* __restrict__ qhi, const __nv_bfloat16* __restrict__ qlo,
    const __nv_bfloat16* __restrict__ khi, const __nv_bfloat16* __restrict__ klo,
    const __nv_bfloat16* __restrict__ vhi, const __nv_bfloat16* __restrict__ vlo,
    __nv_bfloat16* __restrict__ chi, __nv_bfloat16* __restrict__ clo)
{
    extern __shared__ __align__(16) char smraw[];
    __nv_bfloat16* sQh = (__nv_bfloat16*)smraw;
    __nv_bfloat16* sQl = sQh + 64 * LDK;
    __nv_bfloat16* sT  = sQl + 64 * LDK;        // 2 stages x (Kh|Kl|Vh|Vl)
    __shared__ int qdoc[64];
    __shared__ int kdoc[2][64];

    const int tid  = threadIdx.x;
    const int lane = tid & 31;
    const int w    = tid >> 5;
    const int qb = blockIdx.x, h = blockIdx.y, b = blockIdx.z;
    const int kvh = h >> 2;
    const int q0  = qb * 64;
    const int TILE = 64 * LDK;                  // elems per smem tile

    // ---- Q tile (hi/lo) via cp.async ----
    {
        const __nv_bfloat16* srch = qhi + ((size_t)(b * S_ + q0)) * 2048 + h * 64;
        const __nv_bfloat16* srcl = qlo + ((size_t)(b * S_ + q0)) * 2048 + h * 64;
        uint32_t dh = smem_u32(sQh), dl = smem_u32(sQl);
        for (int i = tid; i < 512; i += 128) {
            int r = i >> 3, c = i & 7;
            uint32_t off = (uint32_t)(r * LDK + c * 8) * 2;
            cp16(dh + off, srch + (size_t)r * 2048 + c * 8);
            cp16(dl + off, srcl + (size_t)r * 2048 + c * 8);
        }
        if (tid < 64) qdoc[tid] = doc[b * S_ + q0 + tid];
    }
    cp_commit();

    const int kb0 = g_dstart[b * 8 + doc[b * S_ + q0]] >> 6;

    auto load_kv = [&](int kb, int buf) {
        const size_t row0 = (size_t)(b * S_ + kb * 64);
        const __nv_bfloat16* s0 = khi + row0 * 512 + kvh * 64;
        const __nv_bfloat16* s1 = klo + row0 * 512 + kvh * 64;
        const __nv_bfloat16* s2 = vhi + row0 * 512 + kvh * 64;
        const __nv_bfloat16* s3 = vlo + row0 * 512 + kvh * 64;
        uint32_t d0 = smem_u32(sT + buf * 4 * TILE);
        const uint32_t tb = (uint32_t)TILE * 2;
        for (int i = tid; i < 512; i += 128) {
            int r = i >> 3, c = i & 7;
            uint32_t off = (uint32_t)(r * LDK + c * 8) * 2;
            size_t go = (size_t)r * 512 + c * 8;
            cp16(d0 + off,          s0 + go);
            cp16(d0 + tb + off,     s1 + go);
            cp16(d0 + 2 * tb + off, s2 + go);
            cp16(d0 + 3 * tb + off, s3 + go);
        }
        if (tid < 64) kdoc[buf][tid] = doc[b * S_ + kb * 64 + tid];
    };

    load_kv(kb0, 0);
    cp_commit();

    // Q ready after waiting for the older group
    cp_wait<1>();
    __syncthreads();

    // ---- Q a-frags (persistent) ----
    uint32_t qah[4][4], qal[4][4];
    {
        int row = w * 16 + (lane & 15);
        int col = (lane >> 4) * 8;
#pragma unroll
        for (int s = 0; s < 4; ++s) {
            ldm4(qah[s], smem_u32(sQh + row * LDK + col + s * 16));
            ldm4(qal[s], smem_u32(sQl + row * LDK + col + s * 16));
        }
    }

    const int g   = lane >> 2;
    const int r0g = q0 + w * 16 + g;      // global q index of c0/c1 rows
    const int r1g = r0g + 8;
    const int qd0 = qdoc[w * 16 + g];
    const int qd1 = qdoc[w * 16 + g + 8];

    float m0 = -1e30f, m1 = -1e30f, l0 = 0.f, l1 = 0.f;
    float O[8][4];
#pragma unroll
    for (int j = 0; j < 8; ++j)
#pragma unroll
        for (int e = 0; e < 4; ++e) O[j][e] = 0.f;

    for (int kb = kb0; kb <= qb; ++kb) {
        const int buf = (kb - kb0) & 1;
        cp_wait<0>();
        __syncthreads();
        if (kb < qb) { load_kv(kb + 1, buf ^ 1); cp_commit(); }

        const __nv_bfloat16* Kh = sT + buf * 4 * TILE;
        const __nv_bfloat16* Kl = Kh + TILE;
        const __nv_bfloat16* Vh = Kl + TILE;
        const __nv_bfloat16* Vl = Vh + TILE;

        // ---- S = Q K^T ----
        float Sf[8][4];
#pragma unroll
        for (int j = 0; j < 8; ++j) {
            Sf[j][0] = Sf[j][1] = Sf[j][2] = Sf[j][3] = 0.f;
            uint32_t bh[2][4], bl[2][4];
            int row = j * 8 + (lane & 7);
            int col = (lane >> 3) * 8;
            ldm4(bh[0], smem_u32(Kh + row * LDK + col));
            ldm4(bh[1], smem_u32(Kh + row * LDK + col + 32));
            ldm4(bl[0], smem_u32(Kl + row * LDK + col));
            ldm4(bl[1], smem_u32(Kl + row * LDK + col + 32));
#pragma unroll
            for (int s = 0; s < 4; ++s) {
                int ch = s >> 1, wh = (s & 1) * 2;
                mma16816(Sf[j], qah[s], bh[ch][wh], bh[ch][wh + 1]);
                mma16816(Sf[j], qah[s], bl[ch][wh], bl[ch][wh + 1]);
                mma16816(Sf[j], qal[s], bh[ch][wh], bh[ch][wh + 1]);
            }
        }

        // ---- mask ----
        const int kbase = kb * 64;
#pragma unroll
        for (int j = 0; j < 8; ++j) {
            int cl  = j * 8 + (lane & 3) * 2;
            int c0g = kbase + cl, c1g = c0g + 1;
            int kd0 = kdoc[buf][cl], kd1 = kdoc[buf][cl + 1];
            if (c0g > r0g || kd0 != qd0) Sf[j][0] = -1e30f;
            if (c1g > r0g || kd1 != qd0) Sf[j][1] = -1e30f;
            if (c0g > r1g || kd0 != qd1) Sf[j][2] = -1e30f;
            if (c1g > r1g || kd1 != qd1) Sf[j][3] = -1e30f;
        }

        // ---- online softmax ----
        float t0 = -1e30f, t1 = -1e30f;
#pragma unroll
        for (int j = 0; j < 8; ++j) {
            t0 = fmaxf(t0, fmaxf(Sf[j][0], Sf[j][1]));
            t1 = fmaxf(t1, fmaxf(Sf[j][2], Sf[j][3]));
        }
        t0 = fmaxf(t0, __shfl_xor_sync(0xffffffffu, t0, 1));
        t0 = fmaxf(t0, __shfl_xor_sync(0xffffffffu, t0, 2));
        t1 = fmaxf(t1, __shfl_xor_sync(0xffffffffu, t1, 1));
        t1 = fmaxf(t1, __shfl_xor_sync(0xffffffffu, t1, 2));
        float mn0 = fmaxf(m0, t0), mn1 = fmaxf(m1, t1);
        float corr0 = __expf(m0 - mn0), corr1 = __expf(m1 - mn1);
        m0 = mn0; m1 = mn1;
        float rs0 = 0.f, rs1 = 0.f;
#pragma unroll
        for (int j = 0; j < 8; ++j) {
            Sf[j][0] = __expf(Sf[j][0] - mn0);
            Sf[j][1] = __expf(Sf[j][1] - mn0);
            Sf[j][2] = __expf(Sf[j][2] - mn1);
            Sf[j][3] = __expf(Sf[j][3] - mn1);
            rs0 += Sf[j][0] + Sf[j][1];
            rs1 += Sf[j][2] + Sf[j][3];
        }
        rs0 += __shfl_xor_sync(0xffffffffu, rs0, 1);
        rs0 += __shfl_xor_sync(0xffffffffu, rs0, 2);
        rs1 += __shfl_xor_sync(0xffffffffu, rs1, 1);
        rs1 += __shfl_xor_sync(0xffffffffu, rs1, 2);
        l0 = l0 * corr0 + rs0;
        l1 = l1 * corr1 + rs1;
#pragma unroll
        for (int j = 0; j < 8; ++j) {
            O[j][0] *= corr0; O[j][1] *= corr0;
            O[j][2] *= corr1; O[j][3] *= corr1;
        }

        // ---- P -> a-frags (hi/lo) ----
        uint32_t pah[4][4], pal[4][4];
#pragma unroll
        for (int s = 0; s < 4; ++s) {
            pah[s][0] = packsplit(Sf[2 * s][0],     Sf[2 * s][1],     pal[s][0]);
            pah[s][1] = packsplit(Sf[2 * s][2],     Sf[2 * s][3],     pal[s][1]);
            pah[s][2] = packsplit(Sf[2 * s + 1][0], Sf[2 * s + 1][1], pal[s][2]);
            pah[s][3] = packsplit(Sf[2 * s + 1][2], Sf[2 * s + 1][3], pal[s][3]);
        }

        // ---- O += P V ----
#pragma unroll
        for (int j = 0; j < 8; ++j) {
            uint32_t bvh[2][4], bvl[2][4];
            int vr = lane & 31;
            ldm4t(bvh[0], smem_u32(Vh + vr * LDK + j * 8));
            ldm4t(bvh[1], smem_u32(Vh + (32 + vr) * LDK + j * 8));
            ldm4t(bvl[0], smem_u32(Vl + vr * LDK + j * 8));
            ldm4t(bvl[1], smem_u32(Vl + (32 + vr) * LDK + j * 8));
#pragma unroll
            for (int s = 0; s < 4; ++s) {
                int ch = s >> 1, wh = (s & 1) * 2;
                mma16816(O[j], pah[s], bvh[ch][wh], bvh[ch][wh + 1]);
                mma16816(O[j], pah[s], bvl[ch][wh], bvl[ch][wh + 1]);
                mma16816(O[j], pal[s], bvh[ch][wh], bvh[ch][wh + 1]);
            }
        }
    }

    // ---- epilogue: ctx (bf16 hi/lo) ----
    float inv0 = 1.0f / l0, inv1 = 1.0f / l1;
    __nv_bfloat16* ch0 = chi + ((size_t)(b * S_ + r0g)) * 2048 + h * 64;
    __nv_bfloat16* cl0 = clo + ((size_t)(b * S_ + r0g)) * 2048 + h * 64;
    __nv_bfloat16* ch1 = chi + ((size_t)(b * S_ + r1g)) * 2048 + h * 64;
    __nv_bfloat16* cl1 = clo + ((size_t)(b * S_ + r1g)) * 2048 + h * 64;
#pragma unroll
    for (int j = 0; j < 8; ++j) {
        int col = j * 8 + (lane & 3) * 2;
        uint32_t lo0, lo1;
        uint32_t hi0 = packsplit(O[j][0] * inv0, O[j][1] * inv0, lo0);
        uint32_t hi1 = packsplit(O[j][2] * inv1, O[j][3] * inv1, lo1);
        *(uint32_t*)(ch0 + col) = hi0;
        *(uint32_t*)(cl0 + col) = lo0;
        *(uint32_t*)(ch1 + col) = hi1;
        *(uint32_t*)(cl1 + col) = lo1;
    }
}

// ---------------------------------------------------------------------------
// Host launcher
// ---------------------------------------------------------------------------
extern "C" void kernel_launch(void* const* d_in, const int* in_sizes, int n_in,
                              void* d_out, int out_size)
{
    const float* x   = (const float*)d_in[0];
    const float* rc  = (const float*)d_in[1];
    const float* rs  = (const float*)d_in[2];
    const int*   doc = (const int*)d_in[3];
    const float* Wq  = (const float*)d_in[4];
    const float* Wk  = (const float*)d_in[5];
    const float* Wv  = (const float*)d_in[6];
    const float* Wo  = (const float*)d_in[7];
    float* out = (float*)d_out;

    float *q_p, *k_p, *v_p;
    cudaGetSymbolAddress((void**)&q_p, g_q);
    cudaGetSymbolAddress((void**)&k_p, g_k);
    cudaGetSymbolAddress((void**)&v_p, g_v);

    __nv_bfloat16 *xhi, *xlo, *wqhi, *wqlo, *wkhi, *wklo, *wvhi, *wvlo,
                  *wohi, *wolo, *chi, *clo, *qbh, *qbl, *kbh, *kbl, *vbh, *vbl;
    cudaGetSymbolAddress((void**)&xhi, g_xhi);   cudaGetSymbolAddress((void**)&xlo, g_xlo);
    cudaGetSymbolAddress((void**)&wqhi, g_wqhi); cudaGetSymbolAddress((void**)&wqlo, g_wqlo);
    cudaGetSymbolAddress((void**)&wkhi, g_wkhi); cudaGetSymbolAddress((void**)&wklo, g_wklo);
    cudaGetSymbolAddress((void**)&wvhi, g_wvhi); cudaGetSymbolAddress((void**)&wvlo, g_wvlo);
    cudaGetSymbolAddress((void**)&wohi, g_wohi); cudaGetSymbolAddress((void**)&wolo, g_wolo);
    cudaGetSymbolAddress((void**)&chi, g_chi);   cudaGetSymbolAddress((void**)&clo, g_clo);
    cudaGetSymbolAddress((void**)&qbh, g_qbh);   cudaGetSymbolAddress((void**)&qbl, g_qbl);
    cudaGetSymbolAddress((void**)&kbh, g_kbh);   cudaGetSymbolAddress((void**)&kbl, g_kbl);
    cudaGetSymbolAddress((void**)&vbh, g_vbh);   cudaGetSymbolAddress((void**)&vbl, g_vbl);

    const int flash_smem = (2 * 64 * LDK + 2 * 4 * 64 * LDK) * (int)sizeof(__nv_bfloat16);
    cudaFuncSetAttribute(flash_tc,
                         cudaFuncAttributeMaxDynamicSharedMemorySize, flash_smem);

    // Split inputs to bf16 hi/lo
    {
        int n4;
        n4 = M_ * DIM_ / 4;    split_kernel<<<(n4 + 255) / 256, 256>>>(x,  xhi,  xlo,  n4);
        n4 = DIM_ * DIM_ / 4;  split_kernel<<<(n4 + 255) / 256, 256>>>(Wq, wqhi, wqlo, n4);
        n4 = 512 * DIM_ / 4;   split_kernel<<<(n4 + 255) / 256, 256>>>(Wk, wkhi, wklo, n4);
        n4 = 512 * DIM_ / 4;   split_kernel<<<(n4 + 255) / 256, 256>>>(Wv, wvhi, wvlo, n4);
        n4 = DIM_ * DIM_ / 4;  split_kernel<<<(n4 + 255) / 256, 256>>>(Wo, wohi, wolo, n4);
    }

    // QKV projections (fp32 out)
    {
        dim3 gq(NH_ * HD_ / 128, M_ / 128);
        gemm_bf16split<<<gq, 256>>>(xhi, xlo, wqhi, wqlo, q_p, M_, NH_ * HD_, DIM_);
        dim3 gk(512 / 128, M_ / 128);
        gemm_bf16split<<<gk, 256>>>(xhi, xlo, wkhi, wklo, k_p, M_, 512, DIM_);
        gemm_bf16split<<<gk, 256>>>(xhi, xlo, wvhi, wvlo, v_p, M_, 512, DIM_);
    }

    // RoPE + split to bf16 (Q pre-scaled by 1/sqrt(HD)=0.125)
    {
        int tq = B_ * S_ * NH_ * 32;
        rope_split_kernel<<<(tq + 255) / 256, 256>>>(q_p, rc, rs, qbh, qbl, NH_, tq, 0.125f);
        int tk = B_ * S_ * NKV_ * 32;
        rope_split_kernel<<<(tk + 255) / 256, 256>>>(k_p, rc, rs, kbh, kbl, NKV_, tk, 1.0f);
        int n4 = M_ * 512 / 4;
        split_kernel<<<(n4 + 255) / 256, 256>>>(v_p, vbh, vbl, n4);
    }

    // doc start offsets
    docstart_kernel<<<(B_ * S_ + 255) / 256, 256>>>(doc);

    // tensor-core flash attention -> ctx (bf16 hi/lo)
    {
        dim3 g(S_ / 64, NH_, B_);
        flash_tc<<<g, 128, flash_smem>>>(doc, qbh, qbl, kbh, kbl, vbh, vbl, chi, clo);
    }

    // output projection
    {
        dim3 go(DIM_ / 128, M_ / 128);
        gemm_bf16split<<<go, 256>>>(chi, clo, wohi, wolo, out, M_, DIM_, DIM_);
    }
}

// round 6
// speedup vs baseline: 3.2971x; 1.2244x over previous
#include <cuda_runtime.h>
#include <cuda_bf16.h>
#include <math.h>
#include <stdint.h>

// Problem constants
#define B_    2
#define S_    2048
#define DIM_  2048
#define NH_   32
#define NKV_  8
#define HD_   64
#define M_    (B_ * S_)        // 4096 rows
#define KT_   64               // K tiles (2048/32)
#define TILE_E 5120            // elems per packed 128x32 tile (LDA=40 pitch)

// ---------------------------------------------------------------------------
// Scratch (static device globals — no allocation allowed)
// ---------------------------------------------------------------------------
__device__ float g_qkv[M_ * 3072];        // fused QKV projection output
__device__ int   g_dstart[B_ * 8];

// packed-tile bf16 hi/lo GEMM operands  [tile][128*40]
__device__ __nv_bfloat16 g_xph[32 * KT_ * TILE_E], g_xpl[32 * KT_ * TILE_E];
__device__ __nv_bfloat16 g_wph[24 * KT_ * TILE_E], g_wpl[24 * KT_ * TILE_E];
__device__ __nv_bfloat16 g_woph[16 * KT_ * TILE_E], g_wopl[16 * KT_ * TILE_E];
__device__ __nv_bfloat16 g_cph[32 * KT_ * TILE_E], g_cpl[32 * KT_ * TILE_E];
// flash inputs (row-major bf16 hi/lo, post-rope)
__device__ __nv_bfloat16 g_qbh[M_ * 2048], g_qbl[M_ * 2048];
__device__ __nv_bfloat16 g_kbh[M_ * 512],  g_kbl[M_ * 512];
__device__ __nv_bfloat16 g_vbh[M_ * 512],  g_vbl[M_ * 512];

// ---------------------------------------------------------------------------
// PTX helpers
// ---------------------------------------------------------------------------
__device__ __forceinline__ uint32_t smem_u32(const void* p) {
    uint32_t a;
    asm("{ .reg .u64 t; cvta.to.shared.u64 t, %1; cvt.u32.u64 %0, t; }"
        : "=r"(a) : "l"(p));
    return a;
}
__device__ __forceinline__ void cp16(uint32_t dst, const void* src) {
    asm volatile("cp.async.cg.shared.global [%0], [%1], 16;"
                 :: "r"(dst), "l"(src));
}
__device__ __forceinline__ void cp_commit() {
    asm volatile("cp.async.commit_group;");
}
template<int N>
__device__ __forceinline__ void cp_wait() {
    asm volatile("cp.async.wait_group %0;" :: "n"(N));
}
__device__ __forceinline__ void ldm4(uint32_t* r, uint32_t a) {
    asm volatile("ldmatrix.sync.aligned.m8n8.x4.shared.b16 {%0,%1,%2,%3}, [%4];"
        : "=r"(r[0]), "=r"(r[1]), "=r"(r[2]), "=r"(r[3]) : "r"(a));
}
__device__ __forceinline__ void ldm4t(uint32_t* r, uint32_t a) {
    asm volatile("ldmatrix.sync.aligned.m8n8.x4.trans.shared.b16 {%0,%1,%2,%3}, [%4];"
        : "=r"(r[0]), "=r"(r[1]), "=r"(r[2]), "=r"(r[3]) : "r"(a));
}
__device__ __forceinline__ void mma16816(float* c, const uint32_t* a,
                                         uint32_t b0, uint32_t b1) {
    asm volatile(
        "mma.sync.aligned.m16n8k16.row.col.f32.bf16.bf16.f32 "
        "{%0,%1,%2,%3}, {%4,%5,%6,%7}, {%8,%9}, {%0,%1,%2,%3};"
        : "+f"(c[0]), "+f"(c[1]), "+f"(c[2]), "+f"(c[3])
        : "r"(a[0]), "r"(a[1]), "r"(a[2]), "r"(a[3]), "r"(b0), "r"(b1));
}
__device__ __forceinline__ void mbar_init(uint32_t mbar, uint32_t cnt) {
    asm volatile("mbarrier.init.shared.b64 [%0], %1;" :: "r"(mbar), "r"(cnt) : "memory");
}
__device__ __forceinline__ void mbar_expect(uint32_t mbar, uint32_t bytes) {
    asm volatile("mbarrier.arrive.expect_tx.shared.b64 _, [%0], %1;"
                 :: "r"(mbar), "r"(bytes) : "memory");
}
__device__ __forceinline__ void mbar_wait(uint32_t mbar, uint32_t phase) {
    asm volatile(
        "{\n .reg .pred P;\n"
        "W_%=:\n"
        " mbarrier.try_wait.parity.acquire.cta.shared::cta.b64 P, [%0], %1, 0x989680;\n"
        " @P bra.uni D_%=;\n bra.uni W_%=;\n"
        "D_%=:\n}"
        :: "r"(mbar), "r"(phase) : "memory");
}
__device__ __forceinline__ void bulk_g2s(uint32_t dst, const void* src,
                                         uint32_t bytes, uint32_t mbar) {
    asm volatile(
        "cp.async.bulk.shared::cluster.global.mbarrier::complete_tx::bytes "
        "[%0], [%1], %2, [%3];"
        :: "r"(dst), "l"(src), "r"(bytes), "r"(mbar) : "memory");
}
__device__ __forceinline__ void fence_proxy_async_cta() {
    asm volatile("fence.proxy.async.shared::cta;" ::: "memory");
}
union BF2U { __nv_bfloat162 b; uint32_t u; };
__device__ __forceinline__ uint32_t packsplit(float x, float y, uint32_t& lo) {
    __nv_bfloat16 hx = __float2bfloat16(x), hy = __float2bfloat16(y);
    BF2U H, L;
    H.b.x = hx; H.b.y = hy;
    L.b.x = __float2bfloat16(x - __bfloat162float(hx));
    L.b.y = __float2bfloat16(y - __bfloat162float(hy));
    lo = L.u;
    return H.u;
}

// ---------------------------------------------------------------------------
// fp32 [R,K] row-major -> packed-tile bf16 hi/lo
// tile (r>>7, k>>5): 128 rows x 32 elems, row pitch 40 elems (80B), 16B chunks
// ---------------------------------------------------------------------------
__global__ void splitpack_kernel(const float* __restrict__ src,
                                 __nv_bfloat16* __restrict__ hi,
                                 __nv_bfloat16* __restrict__ lo,
                                 int nchunk, int kchunks)
{
    int i = blockIdx.x * blockDim.x + threadIdx.x;
    if (i >= nchunk) return;
    int r  = i / kchunks;
    int kc = i - r * kchunks;
    const float4* s = (const float4*)src + (size_t)i * 2;
    float4 v0 = s[0], v1 = s[1];
    uint32_t l0, l1, l2, l3;
    uint32_t h0 = packsplit(v0.x, v0.y, l0);
    uint32_t h1 = packsplit(v0.z, v0.w, l1);
    uint32_t h2 = packsplit(v1.x, v1.y, l2);
    uint32_t h3 = packsplit(v1.z, v1.w, l3);
    size_t off = ((size_t)(r >> 7) * (kchunks >> 2) + (kc >> 2)) * TILE_E
               + (r & 127) * 40 + (kc & 3) * 8;
    *(uint4*)(hi + off) = make_uint4(h0, h1, h2, h3);
    *(uint4*)(lo + off) = make_uint4(l0, l1, l2, l3);
}

// ---------------------------------------------------------------------------
// Packed-tile bf16-split GEMM: C[M,N] = A*B^T (fp32 out, row-major)
// CTA 128x128, 4 warps (warp tile 64x64), cp.async.bulk double buffer.
// ---------------------------------------------------------------------------
__global__ __launch_bounds__(128, 2) void gemm_pk(
    const __nv_bfloat16* __restrict__ Ah, const __nv_bfloat16* __restrict__ Al,
    const __nv_bfloat16* __restrict__ Bh, const __nv_bfloat16* __restrict__ Bl,
    float* __restrict__ C, int N, int Ktiles)
{
    __shared__ __align__(128) __nv_bfloat16 sm[2][4][TILE_E];
    __shared__ __align__(8) uint64_t mb[2];

    const int tid = threadIdx.x, lane = tid & 31, w = tid >> 5;
    const int wm = w & 1, wn = w >> 1;

    const uint32_t mbar0 = smem_u32(&mb[0]);
    const uint32_t mbar1 = smem_u32(&mb[1]);
    if (tid == 0) { mbar_init(mbar0, 1); mbar_init(mbar1, 1); }
    __syncthreads();

    const size_t tA = (size_t)blockIdx.y * Ktiles;
    const size_t tB = (size_t)blockIdx.x * Ktiles;

    auto issue = [&](int kt, int buf) {
        uint32_t mbar = buf ? mbar1 : mbar0;
        mbar_expect(mbar, 4 * TILE_E * 2);
        bulk_g2s(smem_u32(sm[buf][0]), Ah + (tA + kt) * TILE_E, TILE_E * 2, mbar);
        bulk_g2s(smem_u32(sm[buf][1]), Al + (tA + kt) * TILE_E, TILE_E * 2, mbar);
        bulk_g2s(smem_u32(sm[buf][2]), Bh + (tB + kt) * TILE_E, TILE_E * 2, mbar);
        bulk_g2s(smem_u32(sm[buf][3]), Bl + (tB + kt) * TILE_E, TILE_E * 2, mbar);
    };
    if (tid == 0) { issue(0, 0); issue(1, 1); }

    float acc[4][8][4];
#pragma unroll
    for (int i = 0; i < 4; ++i)
#pragma unroll
        for (int j = 0; j < 8; ++j)
#pragma unroll
            for (int e = 0; e < 4; ++e) acc[i][j][e] = 0.f;

    int ph0 = 0, ph1 = 0;

    for (int kt = 0; kt < Ktiles; ++kt) {
        const int buf = kt & 1;
        if (buf == 0) { mbar_wait(mbar0, ph0); ph0 ^= 1; }
        else          { mbar_wait(mbar1, ph1); ph1 ^= 1; }

        const __nv_bfloat16* A0 = sm[buf][0];
        const __nv_bfloat16* A1 = sm[buf][1];
        const __nv_bfloat16* B0 = sm[buf][2];
        const __nv_bfloat16* B1 = sm[buf][3];

#pragma unroll
        for (int kk = 0; kk < 2; ++kk) {
            const int achk = kk * 2 + (lane >> 4);
            const int arow = wm * 64 + (lane & 15);
            uint32_t ah[4][4], al[4][4];
#pragma unroll
            for (int mt = 0; mt < 4; ++mt) {
                ldm4(ah[mt], smem_u32(A0 + (arow + mt * 16) * 40 + achk * 8));
                ldm4(al[mt], smem_u32(A1 + (arow + mt * 16) * 40 + achk * 8));
            }
            const int brow = wn * 64 + (lane & 15);
#pragma unroll
            for (int nt = 0; nt < 4; ++nt) {
                uint32_t bh[4], bl[4];
                ldm4(bh, smem_u32(B0 + (brow + nt * 16) * 40 + achk * 8));
                ldm4(bl, smem_u32(B1 + (brow + nt * 16) * 40 + achk * 8));
#pragma unroll
                for (int mt = 0; mt < 4; ++mt) {
                    mma16816(acc[mt][2 * nt],     ah[mt], bh[0], bh[2]);
                    mma16816(acc[mt][2 * nt],     ah[mt], bl[0], bl[2]);
                    mma16816(acc[mt][2 * nt],     al[mt], bh[0], bh[2]);
                    mma16816(acc[mt][2 * nt + 1], ah[mt], bh[1], bh[3]);
                    mma16816(acc[mt][2 * nt + 1], ah[mt], bl[1], bl[3]);
                    mma16816(acc[mt][2 * nt + 1], al[mt], bh[1], bh[3]);
                }
            }
        }
        __syncthreads();
        if (kt + 2 < Ktiles && tid == 0) {
            fence_proxy_async_cta();
            issue(kt + 2, buf);
        }
    }

    // epilogue: fp32 row-major
    const int brow = blockIdx.y * 128 + wm * 64;
    const int bcol = blockIdx.x * 128 + wn * 64;
#pragma unroll
    for (int mt = 0; mt < 4; ++mt) {
        int r0 = brow + mt * 16 + (lane >> 2);
#pragma unroll
        for (int j = 0; j < 8; ++j) {
            int col = bcol + j * 8 + (lane & 3) * 2;
            *(float2*)(C + (size_t)r0 * N + col) =
                make_float2(acc[mt][j][0], acc[mt][j][1]);
            *(float2*)(C + (size_t)(r0 + 8) * N + col) =
                make_float2(acc[mt][j][2], acc[mt][j][3]);
        }
    }
}

// ---------------------------------------------------------------------------
// RoPE + bf16 hi/lo split (reads fused qkv fp32, strided; writes row-major)
// ---------------------------------------------------------------------------
__global__ void rope_split_kernel(const float* __restrict__ t,
                                  const float* __restrict__ cs,
                                  const float* __restrict__ sn,
                                  __nv_bfloat16* __restrict__ hi,
                                  __nv_bfloat16* __restrict__ lo,
                                  int nh, int coloff, int total, float scale)
{
    int i = blockIdx.x * blockDim.x + threadIdx.x;
    if (i >= total) return;
    int d = i & 31;
    int g = i >> 5;
    int h = g % nh;
    int s = (g / nh) % S_;
    int b = g / (nh * S_);
    float c  = cs[s * 32 + d];
    float sv = sn[s * 32 + d];
    size_t in = (size_t)(b * S_ + s) * 3072 + coloff + h * 64;
    size_t o  = ((size_t)(b * S_ + s) * nh + h) * 64;
    float x1 = t[in + d];
    float x2 = t[in + d + 32];
    float y1 = (x1 * c - x2 * sv) * scale;
    float y2 = (x2 * c + x1 * sv) * scale;
    __nv_bfloat16 h1 = __float2bfloat16(y1), h2 = __float2bfloat16(y2);
    hi[o + d]      = h1;
    hi[o + d + 32] = h2;
    lo[o + d]      = __float2bfloat16(y1 - __bfloat162float(h1));
    lo[o + d + 32] = __float2bfloat16(y2 - __bfloat162float(h2));
}

// V split: strided read from fused qkv, row-major bf16 hi/lo out
__global__ void vsplit_kernel(const float* __restrict__ qkv,
                              __nv_bfloat16* __restrict__ hi,
                              __nv_bfloat16* __restrict__ lo, int n4)
{
    int i = blockIdx.x * blockDim.x + threadIdx.x;
    if (i >= n4) return;
    int row = i >> 7;
    int c4  = (i & 127) * 4;
    float4 v = *(const float4*)(qkv + (size_t)row * 3072 + 2560 + c4);
    uint32_t l0, l1;
    uint32_t h0 = packsplit(v.x, v.y, l0);
    uint32_t h1 = packsplit(v.z, v.w, l1);
    *(uint2*)(hi + (size_t)row * 512 + c4) = make_uint2(h0, h1);
    *(uint2*)(lo + (size_t)row * 512 + c4) = make_uint2(l0, l1);
}

// ---------------------------------------------------------------------------
// Doc start scan
// ---------------------------------------------------------------------------
__global__ void docstart_kernel(const int* __restrict__ doc)
{
    int i = blockIdx.x * blockDim.x + threadIdx.x;
    if (i >= B_ * S_) return;
    int s = i & (S_ - 1);
    int d = doc[i];
    if (s == 0 || doc[i - 1] != d) g_dstart[(i >> 11) * 8 + d] = s;
}

// ---------------------------------------------------------------------------
// Tensor-core flash attention (as R5), epilogue writes packed-tile ctx.
// ---------------------------------------------------------------------------
#define LDK 72

__global__ __launch_bounds__(128) void flash_tc(
    const int* __restrict__ doc,
    const __nv_bfloat16* __restrict__ qhi, const __nv_bfloat16* __restrict__ qlo,
    const __nv_bfloat16* __restrict__ khi, const __nv_bfloat16* __restrict__ klo,
    const __nv_bfloat16* __restrict__ vhi, const __nv_bfloat16* __restrict__ vlo,
    __nv_bfloat16* __restrict__ cph, __nv_bfloat16* __restrict__ cpl)
{
    extern __shared__ __align__(16) char smraw[];
    __nv_bfloat16* sQh = (__nv_bfloat16*)smraw;
    __nv_bfloat16* sQl = sQh + 64 * LDK;
    __nv_bfloat16* sT  = sQl + 64 * LDK;
    __shared__ int qdoc[64];
    __shared__ int kdoc[2][64];

    const int tid  = threadIdx.x;
    const int lane = tid & 31;
    const int w    = tid >> 5;
    const int qb = blockIdx.x, h = blockIdx.y, b = blockIdx.z;
    const int kvh = h >> 2;
    const int q0  = qb * 64;
    const int TILE = 64 * LDK;

    {
        const __nv_bfloat16* srch = qhi + ((size_t)(b * S_ + q0)) * 2048 + h * 64;
        const __nv_bfloat16* srcl = qlo + ((size_t)(b * S_ + q0)) * 2048 + h * 64;
        uint32_t dh = smem_u32(sQh), dl = smem_u32(sQl);
        for (int i = tid; i < 512; i += 128) {
            int r = i >> 3, c = i & 7;
            uint32_t off = (uint32_t)(r * LDK + c * 8) * 2;
            cp16(dh + off, srch + (size_t)r * 2048 + c * 8);
            cp16(dl + off, srcl + (size_t)r * 2048 + c * 8);
        }
        if (tid < 64) qdoc[tid] = doc[b * S_ + q0 + tid];
    }
    cp_commit();

    const int kb0 = g_dstart[b * 8 + doc[b * S_ + q0]] >> 6;

    auto load_kv = [&](int kb, int buf) {
        const size_t row0 = (size_t)(b * S_ + kb * 64);
        const __nv_bfloat16* s0 = khi + row0 * 512 + kvh * 64;
        const __nv_bfloat16* s1 = klo + row0 * 512 + kvh * 64;
        const __nv_bfloat16* s2 = vhi + row0 * 512 + kvh * 64;
        const __nv_bfloat16* s3 = vlo + row0 * 512 + kvh * 64;
        uint32_t d0 = smem_u32(sT + buf * 4 * TILE);
        const uint32_t tb = (uint32_t)TILE * 2;
        for (int i = tid; i < 512; i += 128) {
            int r = i >> 3, c = i & 7;
            uint32_t off = (uint32_t)(r * LDK + c * 8) * 2;
            size_t go = (size_t)r * 512 + c * 8;
            cp16(d0 + off,          s0 + go);
            cp16(d0 + tb + off,     s1 + go);
            cp16(d0 + 2 * tb + off, s2 + go);
            cp16(d0 + 3 * tb + off, s3 + go);
        }
        if (tid < 64) kdoc[buf][tid] = doc[b * S_ + kb * 64 + tid];
    };

    load_kv(kb0, 0);
    cp_commit();
    cp_wait<1>();
    __syncthreads();

    uint32_t qah[4][4], qal[4][4];
    {
        int row = w * 16 + (lane & 15);
        int col = (lane >> 4) * 8;
#pragma unroll
        for (int s = 0; s < 4; ++s) {
            ldm4(qah[s], smem_u32(sQh + row * LDK + col + s * 16));
            ldm4(qal[s], smem_u32(sQl + row * LDK + col + s * 16));
        }
    }

    const int g   = lane >> 2;
    const int r0g = q0 + w * 16 + g;
    const int r1g = r0g + 8;
    const int qd0 = qdoc[w * 16 + g];
    const int qd1 = qdoc[w * 16 + g + 8];

    float m0 = -1e30f, m1 = -1e30f, l0 = 0.f, l1 = 0.f;
    float O[8][4];
#pragma unroll
    for (int j = 0; j < 8; ++j)
#pragma unroll
        for (int e = 0; e < 4; ++e) O[j][e] = 0.f;

    for (int kb = kb0; kb <= qb; ++kb) {
        const int buf = (kb - kb0) & 1;
        cp_wait<0>();
        __syncthreads();
        if (kb < qb) { load_kv(kb + 1, buf ^ 1); cp_commit(); }

        const __nv_bfloat16* Kh = sT + buf * 4 * TILE;
        const __nv_bfloat16* Kl = Kh + TILE;
        const __nv_bfloat16* Vh = Kl + TILE;
        const __nv_bfloat16* Vl = Vh + TILE;

        float Sf[8][4];
#pragma unroll
        for (int j = 0; j < 8; ++j) {
            Sf[j][0] = Sf[j][1] = Sf[j][2] = Sf[j][3] = 0.f;
            uint32_t bh[2][4], bl[2][4];
            int row = j * 8 + (lane & 7);
            int col = (lane >> 3) * 8;
            ldm4(bh[0], smem_u32(Kh + row * LDK + col));
            ldm4(bh[1], smem_u32(Kh + row * LDK + col + 32));
            ldm4(bl[0], smem_u32(Kl + row * LDK + col));
            ldm4(bl[1], smem_u32(Kl + row * LDK + col + 32));
#pragma unroll
            for (int s = 0; s < 4; ++s) {
                int ch = s >> 1, wh = (s & 1) * 2;
                mma16816(Sf[j], qah[s], bh[ch][wh], bh[ch][wh + 1]);
                mma16816(Sf[j], qah[s], bl[ch][wh], bl[ch][wh + 1]);
                mma16816(Sf[j], qal[s], bh[ch][wh], bh[ch][wh + 1]);
            }
        }

        const int kbase = kb * 64;
#pragma unroll
        for (int j = 0; j < 8; ++j) {
            int cl  = j * 8 + (lane & 3) * 2;
            int c0g = kbase + cl, c1g = c0g + 1;
            int kd0 = kdoc[buf][cl], kd1 = kdoc[buf][cl + 1];
            if (c0g > r0g || kd0 != qd0) Sf[j][0] = -1e30f;
            if (c1g > r0g || kd1 != qd0) Sf[j][1] = -1e30f;
            if (c0g > r1g || kd0 != qd1) Sf[j][2] = -1e30f;
            if (c1g > r1g || kd1 != qd1) Sf[j][3] = -1e30f;
        }

        float t0 = -1e30f, t1 = -1e30f;
#pragma unroll
        for (int j = 0; j < 8; ++j) {
            t0 = fmaxf(t0, fmaxf(Sf[j][0], Sf[j][1]));
            t1 = fmaxf(t1, fmaxf(Sf[j][2], Sf[j][3]));
        }
        t0 = fmaxf(t0, __shfl_xor_sync(0xffffffffu, t0, 1));
        t0 = fmaxf(t0, __shfl_xor_sync(0xffffffffu, t0, 2));
        t1 = fmaxf(t1, __shfl_xor_sync(0xffffffffu, t1, 1));
        t1 = fmaxf(t1, __shfl_xor_sync(0xffffffffu, t1, 2));
        float mn0 = fmaxf(m0, t0), mn1 = fmaxf(m1, t1);
        float corr0 = __expf(m0 - mn0), corr1 = __expf(m1 - mn1);
        m0 = mn0; m1 = mn1;
        float rs0 = 0.f, rs1 = 0.f;
#pragma unroll
        for (int j = 0; j < 8; ++j) {
            Sf[j][0] = __expf(Sf[j][0] - mn0);
            Sf[j][1] = __expf(Sf[j][1] - mn0);
            Sf[j][2] = __expf(Sf[j][2] - mn1);
            Sf[j][3] = __expf(Sf[j][3] - mn1);
            rs0 += Sf[j][0] + Sf[j][1];
            rs1 += Sf[j][2] + Sf[j][3];
        }
        rs0 += __shfl_xor_sync(0xffffffffu, rs0, 1);
        rs0 += __shfl_xor_sync(0xffffffffu, rs0, 2);
        rs1 += __shfl_xor_sync(0xffffffffu, rs1, 1);
        rs1 += __shfl_xor_sync(0xffffffffu, rs1, 2);
        l0 = l0 * corr0 + rs0;
        l1 = l1 * corr1 + rs1;
#pragma unroll
        for (int j = 0; j < 8; ++j) {
            O[j][0] *= corr0; O[j][1] *= corr0;
            O[j][2] *= corr1; O[j][3] *= corr1;
        }

        uint32_t pah[4][4], pal[4][4];
#pragma unroll
        for (int s = 0; s < 4; ++s) {
            pah[s][0] = packsplit(Sf[2 * s][0],     Sf[2 * s][1],     pal[s][0]);
            pah[s][1] = packsplit(Sf[2 * s][2],     Sf[2 * s][3],     pal[s][1]);
            pah[s][2] = packsplit(Sf[2 * s + 1][0], Sf[2 * s + 1][1], pal[s][2]);
            pah[s][3] = packsplit(Sf[2 * s + 1][2], Sf[2 * s + 1][3], pal[s][3]);
        }

#pragma unroll
        for (int j = 0; j < 8; ++j) {
            uint32_t bvh[2][4], bvl[2][4];
            int vr = lane & 31;
            ldm4t(bvh[0], smem_u32(Vh + vr * LDK + j * 8));
            ldm4t(bvh[1], smem_u32(Vh + (32 + vr) * LDK + j * 8));
            ldm4t(bvl[0], smem_u32(Vl + vr * LDK + j * 8));
            ldm4t(bvl[1], smem_u32(Vl + (32 + vr) * LDK + j * 8));
#pragma unroll
            for (int s = 0; s < 4; ++s) {
                int ch = s >> 1, wh = (s & 1) * 2;
                mma16816(O[j], pah[s], bvh[ch][wh], bvh[ch][wh + 1]);
                mma16816(O[j], pah[s], bvl[ch][wh], bvl[ch][wh + 1]);
                mma16816(O[j], pal[s], bvh[ch][wh], bvh[ch][wh + 1]);
            }
        }
    }

    // ---- epilogue: write ctx in packed-tile layout ----
    float inv0 = 1.0f / l0, inv1 = 1.0f / l1;
    int grow0 = b * S_ + r0g;
    int grow1 = grow0 + 8;
#pragma unroll
    for (int j = 0; j < 8; ++j) {
        int col = h * 64 + j * 8 + (lane & 3) * 2;
        size_t tbase = ((size_t)(grow0 >> 7) * KT_ + (col >> 5)) * TILE_E
                     + ((col >> 3) & 3) * 8 + (col & 7);
        size_t o0 = tbase + (grow0 & 127) * 40;
        size_t o1 = tbase + (grow1 & 127) * 40;
        uint32_t lo0, lo1;
        uint32_t hi0 = packsplit(O[j][0] * inv0, O[j][1] * inv0, lo0);
        uint32_t hi1 = packsplit(O[j][2] * inv1, O[j][3] * inv1, lo1);
        *(uint32_t*)(cph + o0) = hi0;
        *(uint32_t*)(cpl + o0) = lo0;
        *(uint32_t*)(cph + o1) = hi1;
        *(uint32_t*)(cpl + o1) = lo1;
    }
}

// ---------------------------------------------------------------------------
// Host launcher
// ---------------------------------------------------------------------------
extern "C" void kernel_launch(void* const* d_in, const int* in_sizes, int n_in,
                              void* d_out, int out_size)
{
    const float* x   = (const float*)d_in[0];
    const float* rc  = (const float*)d_in[1];
    const float* rs  = (const float*)d_in[2];
    const int*   doc = (const int*)d_in[3];
    const float* Wq  = (const float*)d_in[4];
    const float* Wk  = (const float*)d_in[5];
    const float* Wv  = (const float*)d_in[6];
    const float* Wo  = (const float*)d_in[7];
    float* out = (float*)d_out;

    float* qkv_p;
    cudaGetSymbolAddress((void**)&qkv_p, g_qkv);

    __nv_bfloat16 *xph, *xpl, *wph, *wpl, *woph, *wopl, *cph, *cpl,
                  *qbh, *qbl, *kbh, *kbl, *vbh, *vbl;
    cudaGetSymbolAddress((void**)&xph, g_xph);   cudaGetSymbolAddress((void**)&xpl, g_xpl);
    cudaGetSymbolAddress((void**)&wph, g_wph);   cudaGetSymbolAddress((void**)&wpl, g_wpl);
    cudaGetSymbolAddress((void**)&woph, g_woph); cudaGetSymbolAddress((void**)&wopl, g_wopl);
    cudaGetSymbolAddress((void**)&cph, g_cph);   cudaGetSymbolAddress((void**)&cpl, g_cpl);
    cudaGetSymbolAddress((void**)&qbh, g_qbh);   cudaGetSymbolAddress((void**)&qbl, g_qbl);
    cudaGetSymbolAddress((void**)&kbh, g_kbh);   cudaGetSymbolAddress((void**)&kbl, g_kbl);
    cudaGetSymbolAddress((void**)&vbh, g_vbh);   cudaGetSymbolAddress((void**)&vbl, g_vbl);

    const int flash_smem = (2 * 64 * LDK + 2 * 4 * 64 * LDK) * (int)sizeof(__nv_bfloat16);
    cudaFuncSetAttribute(flash_tc,
                         cudaFuncAttributeMaxDynamicSharedMemorySize, flash_smem);

    // Pack inputs to tile-contiguous bf16 hi/lo
    {
        const size_t wk_off = (size_t)16 * KT_ * TILE_E;
        const size_t wv_off = (size_t)20 * KT_ * TILE_E;
        int nc;
        nc = M_ * 256;   splitpack_kernel<<<(nc + 255) / 256, 256>>>(x,  xph, xpl, nc, 256);
        nc = 2048 * 256; splitpack_kernel<<<(nc + 255) / 256, 256>>>(Wq, wph, wpl, nc, 256);
        nc = 512 * 256;  splitpack_kernel<<<(nc + 255) / 256, 256>>>(Wk, wph + wk_off, wpl + wk_off, nc, 256);
        nc = 512 * 256;  splitpack_kernel<<<(nc + 255) / 256, 256>>>(Wv, wph + wv_off, wpl + wv_off, nc, 256);
        nc = 2048 * 256; splitpack_kernel<<<(nc + 255) / 256, 256>>>(Wo, woph, wopl, nc, 256);
    }

    // Fused QKV projection: [4096,3072] = x @ [Wq;Wk;Wv]^T
    {
        dim3 g(3072 / 128, M_ / 128);  // (24, 32)
        gemm_pk<<<g, 128>>>(xph, xpl, wph, wpl, qkv_p, 3072, KT_);
    }

    // RoPE + split (Q pre-scaled by 0.125), V split
    {
        int tq = B_ * S_ * NH_ * 32;
        rope_split_kernel<<<(tq + 255) / 256, 256>>>(qkv_p, rc, rs, qbh, qbl, NH_, 0, tq, 0.125f);
        int tk = B_ * S_ * NKV_ * 32;
        rope_split_kernel<<<(tk + 255) / 256, 256>>>(qkv_p, rc, rs, kbh, kbl, NKV_, 2048, tk, 1.0f);
        int n4 = M_ * 512 / 4;
        vsplit_kernel<<<(n4 + 255) / 256, 256>>>(qkv_p, vbh, vbl, n4);
    }

    // doc start offsets
    docstart_kernel<<<(B_ * S_ + 255) / 256, 256>>>(doc);

    // tensor-core flash attention -> packed ctx
    {
        dim3 g(S_ / 64, NH_, B_);
        flash_tc<<<g, 128, flash_smem>>>(doc, qbh, qbl, kbh, kbl, vbh, vbl, cph, cpl);
    }

    // output projection: out = ctx @ Wo^T
    {
        dim3 g(2048 / 128, M_ / 128);  // (16, 32)
        gemm_pk<<<g, 128>>>(cph, cpl, woph, wopl, out, 2048, KT_);
    }
}